// round 13
// baseline (speedup 1.0000x reference)
#include <cuda_runtime.h>
#include <cuda_bf16.h>
#include <cuda_fp16.h>
#include <math.h>
#include <stdint.h>

// ================= scratch (device globals) =================
__device__ float g_q[6291456];                         // [B*H][4096][64] fp32
__device__ __nv_bfloat16 g_k_hi[6291456], g_k_lo[6291456];      // attn operands (bf16)
__device__ __nv_bfloat16 g_v_hi[6291456], g_v_lo[6291456];
__device__ __nv_bfloat16 g_relk_hi[12 * 1023 * 64], g_relk_lo[12 * 1023 * 64];

__device__ __half g_x_hi[8192 * 768],    g_x_lo[8192 * 768];    // GEMM operands (fp16)
__device__ __half g_wqkv_hi[2304 * 768], g_wqkv_lo[2304 * 768]; // [N][K]
__device__ __half g_wout_hi[768 * 768],  g_wout_lo[768 * 768];
__device__ __half g_wrel_hi[768 * 768],  g_wrel_lo[768 * 768];
__device__ __half g_pos_hi[1024 * 768],  g_pos_lo[1024 * 768];  // row 1023 stays zero
__device__ __half g_att_hi[8192 * 768],  g_att_lo[8192 * 768];

// ================= helpers =================
__device__ __forceinline__ uint32_t smem_u32(const void* p) {
    uint32_t a;
    asm("{ .reg .u64 t; cvta.to.shared.u64 t, %1; cvt.u32.u64 %0, t; }" : "=r"(a) : "l"(p));
    return a;
}
__device__ __forceinline__ void cp_async16(uint32_t dst, const void* src) {
    asm volatile("cp.async.ca.shared.global [%0], [%1], 16;" :: "r"(dst), "l"(src));
}
__device__ __forceinline__ void cp_commit() { asm volatile("cp.async.commit_group;"); }
__device__ __forceinline__ void cp_wait1() { asm volatile("cp.async.wait_group 1;"); }
__device__ __forceinline__ void cp_wait0() { asm volatile("cp.async.wait_group 0;"); }

__device__ __forceinline__ void ldsm4(uint32_t* r, uint32_t addr) {
    asm volatile("ldmatrix.sync.aligned.m8n8.x4.shared.b16 {%0,%1,%2,%3}, [%4];"
                 : "=r"(r[0]), "=r"(r[1]), "=r"(r[2]), "=r"(r[3]) : "r"(addr));
}
__device__ __forceinline__ void ldsm4t(uint32_t* r, uint32_t addr) {
    asm volatile("ldmatrix.sync.aligned.m8n8.x4.trans.shared.b16 {%0,%1,%2,%3}, [%4];"
                 : "=r"(r[0]), "=r"(r[1]), "=r"(r[2]), "=r"(r[3]) : "r"(addr));
}
// bf16 MMA (attention path)
__device__ __forceinline__ void mma16816(float* d, const uint32_t* a, uint32_t b0, uint32_t b1) {
    asm volatile("mma.sync.aligned.m16n8k16.row.col.f32.bf16.bf16.f32 "
                 "{%0,%1,%2,%3}, {%4,%5,%6,%7}, {%8,%9}, {%0,%1,%2,%3};"
                 : "+f"(d[0]), "+f"(d[1]), "+f"(d[2]), "+f"(d[3])
                 : "r"(a[0]), "r"(a[1]), "r"(a[2]), "r"(a[3]), "r"(b0), "r"(b1));
}
// fp16 MMA with fp32 accumulate (GEMM main product)
__device__ __forceinline__ void mma_f16f32(float* d, const uint32_t* a, uint32_t b0, uint32_t b1) {
    asm volatile("mma.sync.aligned.m16n8k16.row.col.f32.f16.f16.f32 "
                 "{%0,%1,%2,%3}, {%4,%5,%6,%7}, {%8,%9}, {%0,%1,%2,%3};"
                 : "+f"(d[0]), "+f"(d[1]), "+f"(d[2]), "+f"(d[3])
                 : "r"(a[0]), "r"(a[1]), "r"(a[2]), "r"(a[3]), "r"(b0), "r"(b1));
}
// fp16 MMA with fp16 accumulate (GEMM correction products)
__device__ __forceinline__ void mma_f16f16(uint32_t* d, const uint32_t* a, uint32_t b0, uint32_t b1) {
    asm volatile("mma.sync.aligned.m16n8k16.row.col.f16.f16.f16.f16 "
                 "{%0,%1}, {%2,%3,%4,%5}, {%6,%7}, {%0,%1};"
                 : "+r"(d[0]), "+r"(d[1])
                 : "r"(a[0]), "r"(a[1]), "r"(a[2]), "r"(a[3]), "r"(b0), "r"(b1));
}
__device__ __forceinline__ void split2(float v, __nv_bfloat16& h, __nv_bfloat16& l) {
    h = __float2bfloat16(v);
    l = __float2bfloat16(v - __bfloat162float(h));
}
__device__ __forceinline__ void split2h(float v, __half& h, __half& l) {
    h = __float2half_rn(v);
    l = __float2half_rn(v - __half2float(h));
}
// bf16 pack (attention P/Q smem path)
__device__ __forceinline__ uint32_t pack_split(float a, float b, uint32_t& lo) {
    uint32_t h;
    asm("cvt.rn.bf16x2.f32 %0, %1, %2;" : "=r"(h) : "f"(b), "f"(a));
    float ra = __uint_as_float(h << 16);
    float rb = __uint_as_float(h & 0xffff0000u);
    asm("cvt.rn.bf16x2.f32 %0, %1, %2;" : "=r"(lo) : "f"(b - rb), "f"(a - ra));
    return h;
}
// fp16 pack (g_att store for out-proj)
__device__ __forceinline__ uint32_t pack_splith(float a, float b, uint32_t& lo) {
    __half2 h = __floats2half2_rn(a, b);
    float ra = __half2float(__low2half(h));
    float rb = __half2float(__high2half(h));
    __half2 l = __floats2half2_rn(a - ra, b - rb);
    lo = *(uint32_t*)&l;
    return *(uint32_t*)&h;
}

// ================= kernel 1: merged prologue =================
__device__ __forceinline__ void splitT_body(const float* __restrict__ src,
                                            __half* __restrict__ hi,
                                            __half* __restrict__ lo,
                                            int K, int N, int bx, int by, int tid,
                                            float (*t)[33]) {
    int n0 = bx * 32, k0 = by * 32;
    int x = tid & 31, y0 = tid >> 5;
#pragma unroll
    for (int i = 0; i < 4; i++) {
        int y = y0 + i * 8;
        t[y][x] = src[(size_t)(k0 + y) * N + n0 + x];
    }
    __syncthreads();
#pragma unroll
    for (int i = 0; i < 4; i++) {
        int y = y0 + i * 8;
        float v = t[x][y];
        __half a, b;
        split2h(v, a, b);
        size_t o = (size_t)(n0 + y) * K + k0 + x;
        hi[o] = a; lo[o] = b;
    }
}

__global__ __launch_bounds__(256) void prep_kernel(
    const float* __restrict__ x, const float* __restrict__ w_qkv,
    const float* __restrict__ w_out, const float* __restrict__ w_rel)
{
    __shared__ float t[32][33];
    __shared__ double red[2][128];
    int bid = blockIdx.x, tid = threadIdx.x;

    if (bid < 2048) {
#pragma unroll
        for (int it = 0; it < 12; it++) {
            int i = (bid * 12 + it) * 256 + tid;
            split2h(x[i], g_x_hi[i], g_x_lo[i]);
        }
    } else if (bid < 3776) {
        int rid = bid - 2048;
        splitT_body(w_qkv, g_wqkv_hi, g_wqkv_lo, 768, 2304, rid % 72, rid / 72, tid, t);
    } else if (bid < 4352) {
        int rid = bid - 3776;
        splitT_body(w_out, g_wout_hi, g_wout_lo, 768, 768, rid % 24, rid / 24, tid, t);
    } else if (bid < 4928) {
        int rid = bid - 4352;
        splitT_body(w_rel, g_wrel_hi, g_wrel_lo, 768, 768, rid % 24, rid / 24, tid, t);
    } else {
        int half = tid >> 7, j = tid & 127;
        int r = (bid - 4928) * 2 + half;
        int rr = (r < 1023) ? r : 1022;
        float dist = (float)(rr - 511);
        double p = fabs((double)dist);

        double hl = exp2(3.0 + (double)j * (6.0 / 127.0));
        float ef = (float)exp(-0.6931471805599453 / hl * p);

        float cw = exp2f((float)(j + 1)) - 1.0f;
        float cm = (cw > (float)p) ? 1.0f : 0.0f;

        double mean = 4.0 * (double)(j + 1);
        double conc = (mean * 0.5) * (mean * 0.5);
        double rate = mean * 0.25;
        double lp = -rate * p - (lgamma(conc) - conc * log(rate));
        if (p > 0.0) lp += (conc - 1.0) * log(p);
        double prob = ((p > 0.0) ? exp(lp) : 0.0) + 1e-8;  // xlogy(c-1,0) -> -inf -> 0

        red[half][j] = prob;
        __syncthreads();
        for (int o = 64; o > 0; o >>= 1) {
            if (j < o) red[half][j] = fmax(red[half][j], red[half][j + o]);
            __syncthreads();
        }
        float gf = (float)(prob / red[half][0]);

        float sg = (dist > 0.f) ? 1.f : ((dist < 0.f) ? -1.f : 0.f);
        float vals[6] = {ef, cm, gf, sg * ef, sg * cm, sg * gf};
        if (r < 1023) {
            size_t base = (size_t)r * 768;
#pragma unroll
            for (int s = 0; s < 6; s++) {
                __half h, l;
                split2h(vals[s], h, l);
                g_pos_hi[base + s * 128 + j] = h;
                g_pos_lo[base + s * 128 + j] = l;
            }
        }
    }
}

// ================= fp16-split GEMM body (128x96 tile) =================
// Main product AhBh -> fp32 accum; corrections AhBl + AlBh -> shared fp16 accum.
#define APB 10240
#define BPB 7680
#define STG 35840
#define GEMM_SMEM (2 * STG)
#define S_ST 100

__device__ __forceinline__ void mma_gemm_body(
    int bx, int by,
    const __half* __restrict__ Ah, const __half* __restrict__ Al,
    const __half* __restrict__ Bh, const __half* __restrict__ Bl,
    const float* __restrict__ bias, float* __restrict__ Cout, int mode)
{
    extern __shared__ char dsm[];
    uint32_t sbase = smem_u32(dsm);
    int tid = threadIdx.x, wid = tid >> 5, lane = tid & 31;
    int wm = wid & 3, wn = wid >> 2;

    size_t m0 = (size_t)by * 128;
    int n0 = bx * 96;

    float acc[2][6][4];
    uint32_t acch[2][6][2];
#pragma unroll
    for (int i = 0; i < 2; i++)
#pragma unroll
        for (int j = 0; j < 6; j++) {
#pragma unroll
            for (int q = 0; q < 4; q++) acc[i][j][q] = 0.f;
            acch[i][j][0] = 0u; acch[i][j][1] = 0u;
        }

    int a_lr = lane & 15;
    int a_lc = (lane >> 4) << 3;
    int b_ln = ((lane >> 4) << 3) + (lane & 7);
    int b_lk = lane & 8;

    auto fill = [&](int s, int c) {
        uint32_t st = sbase + s * STG;
        int k0 = c * 32;
#pragma unroll
        for (int ii = 0; ii < 7; ii++) {
            int i = tid + ii * 256;
            if (i < 1024) {
                int part = i >> 9, rr = (i >> 2) & 127, cc = i & 3;
                const __half* src = (part ? Al : Ah) + (m0 + rr) * 768 + k0 + cc * 8;
                cp_async16(st + part * APB + rr * 80 + cc * 16, src);
            } else {
                int j = i - 1024;
                int part = j >= 384; int jj = j - (part ? 384 : 0);
                int rr = jj >> 2, cc = jj & 3;
                const __half* src = (part ? Bl : Bh) + (size_t)(n0 + rr) * 768 + k0 + cc * 8;
                cp_async16(st + 2 * APB + part * BPB + rr * 80 + cc * 16, src);
            }
        }
        cp_commit();
    };

    fill(0, 0);
    for (int c = 0; c < 24; c++) {
        if (c < 23) { fill((c + 1) & 1, c + 1); cp_wait1(); } else { cp_wait0(); }
        __syncthreads();

        uint32_t st = sbase + (c & 1) * STG;
#pragma unroll
        for (int step = 0; step < 2; step++) {
            uint32_t ab = st + (wm * 32 + a_lr) * 80 + (step * 16 + a_lc) * 2;
            uint32_t bb = st + 2 * APB + (wn * 48 + b_ln) * 80 + (step * 16 + b_lk) * 2;
            uint32_t Af[2][4], Alf[2][4], Bf[3][4], Blf[3][4];
            ldsm4(Af[0], ab);           ldsm4(Af[1], ab + 1280);
            ldsm4(Alf[0], ab + APB);    ldsm4(Alf[1], ab + APB + 1280);
#pragma unroll
            for (int ng = 0; ng < 3; ng++) {
                ldsm4(Bf[ng],  bb + ng * 1280);
                ldsm4(Blf[ng], bb + BPB + ng * 1280);
            }
            // main product (fp32 accum)
#pragma unroll
            for (int mi = 0; mi < 2; mi++)
#pragma unroll
                for (int ng = 0; ng < 3; ng++) {
                    mma_f16f32(acc[mi][ng * 2 + 0], Af[mi], Bf[ng][0], Bf[ng][1]);
                    mma_f16f32(acc[mi][ng * 2 + 1], Af[mi], Bf[ng][2], Bf[ng][3]);
                }
            // corrections (fp16 accum): Ah*Bl then Al*Bh
#pragma unroll
            for (int mi = 0; mi < 2; mi++)
#pragma unroll
                for (int ng = 0; ng < 3; ng++) {
                    mma_f16f16(acch[mi][ng * 2 + 0], Af[mi], Blf[ng][0], Blf[ng][1]);
                    mma_f16f16(acch[mi][ng * 2 + 1], Af[mi], Blf[ng][2], Blf[ng][3]);
                }
#pragma unroll
            for (int mi = 0; mi < 2; mi++)
#pragma unroll
                for (int ng = 0; ng < 3; ng++) {
                    mma_f16f16(acch[mi][ng * 2 + 0], Alf[mi], Bf[ng][0], Bf[ng][1]);
                    mma_f16f16(acch[mi][ng * 2 + 1], Alf[mi], Bf[ng][2], Bf[ng][3]);
                }
        }
        __syncthreads();
    }

    // stage accumulators (main + corrections) to smem S[128][100]
    float* S = (float*)dsm;
#pragma unroll
    for (int mi = 0; mi < 2; mi++)
#pragma unroll
        for (int nj = 0; nj < 6; nj++) {
            int row = wm * 32 + mi * 16 + (lane >> 2);
            int col = wn * 48 + nj * 8 + (lane & 3) * 2;
            __half2 c01 = *(__half2*)&acch[mi][nj][0];
            __half2 c23 = *(__half2*)&acch[mi][nj][1];
            S[row * S_ST + col]             = acc[mi][nj][0] + __half2float(__low2half(c01));
            S[row * S_ST + col + 1]         = acc[mi][nj][1] + __half2float(__high2half(c01));
            S[(row + 8) * S_ST + col]       = acc[mi][nj][2] + __half2float(__low2half(c23));
            S[(row + 8) * S_ST + col + 1]   = acc[mi][nj][3] + __half2float(__high2half(c23));
        }
    __syncthreads();

    if (mode == 0) {
        int hh = bx >> 1;
        int dbase = (bx & 1) * 32;
        int bi = (int)(m0 >> 12);
        int nn0 = (int)(m0 & 4095);
        size_t ob = ((size_t)(bi * 12 + hh) * 4096 + nn0) * 64 + dbase;
        for (int task = wid; task < 384; task += 8) {
            int mm = task / 3;
            int which = task - 3 * mm;
            float v = S[mm * S_ST + 3 * lane + which];
            size_t o = ob + (size_t)mm * 64 + lane;
            if (which == 0) g_q[o] = v;
            else {
                __nv_bfloat16 hv, lv; split2(v, hv, lv);
                if (which == 1) { g_k_hi[o] = hv; g_k_lo[o] = lv; }
                else            { g_v_hi[o] = hv; g_v_lo[o] = lv; }
            }
        }
    } else if (mode == 1) {
        for (int task = wid; task < 384; task += 8) {
            int mm = task / 3;
            int g = task - 3 * mm;
            int cgl = n0 + g * 32 + lane;
            int hh = cgl >> 6, d = cgl & 63;
            int r = (int)m0 + mm;
            if (r < 1023) {
                __nv_bfloat16 hv, lv; split2(S[mm * S_ST + g * 32 + lane], hv, lv);
                size_t o = ((size_t)hh * 1023 + r) * 64 + d;
                g_relk_hi[o] = hv; g_relk_lo[o] = lv;
            }
        }
    } else {
        for (int task = wid; task < 384; task += 8) {
            int mm = task / 3;
            int g = task - 3 * mm;
            int j = g * 32 + lane;
            Cout[(m0 + mm) * 768 + n0 + j] = S[mm * S_ST + j] + bias[n0 + j];
        }
    }
}

// merged QKV (1536 blocks) + relk (64 blocks), 1D grid of 1600
__global__ __launch_bounds__(256) void mma_gemm_merged() {
    int bid = blockIdx.x;
    if (bid < 1536)
        mma_gemm_body(bid % 24, bid / 24, g_x_hi, g_x_lo, g_wqkv_hi, g_wqkv_lo,
                      nullptr, nullptr, 0);
    else {
        int rid = bid - 1536;
        mma_gemm_body(rid % 8, rid / 8, g_pos_hi, g_pos_lo, g_wrel_hi, g_wrel_lo,
                      nullptr, nullptr, 1);
    }
}

// out-proj
__global__ __launch_bounds__(256) void mma_gemm_out(const float* __restrict__ bias,
                                                    float* __restrict__ Cout) {
    mma_gemm_body(blockIdx.x, blockIdx.y, g_att_hi, g_att_lo, g_wout_hi, g_wout_lo,
                  bias, Cout, 2);
}

// ================= kernel 3: tensor-core fused window attention (bf16x3, unchanged) =================
#define OFF_QCH 132096
#define OFF_KV  168960
#define OFF_RS  224256
#define ATT_SMEM 224512

__global__ __launch_bounds__(256) void attn_kernel(const float* __restrict__ rcb,
                                                   const float* __restrict__ rpb)
{
    extern __shared__ char smb[];
    float* S = (float*)smb;
    float* rs = (float*)(smb + OFF_RS);
    uint32_t sb = smem_u32(smb);
    int tid = threadIdx.x, wid = tid >> 5, lane = tid & 31;
    int wm = wid & 1, wn = wid >> 1;

    int tt = blockIdx.x & 7, win = blockIdx.x >> 3;
    int bN = win / 96, rem = win - bN * 96, h = rem >> 3, w = rem & 7;
    int t0 = tt << 6;
    size_t base = ((size_t)(bN * 12 + h)) * 4096 + (size_t)w * 512;
    const float* qb = g_q + (base + t0) * 64;
    const __nv_bfloat16 *kh = g_k_hi + base * 64, *klp = g_k_lo + base * 64;
    const __nv_bfloat16 *vh = g_v_hi + base * 64, *vlp = g_v_lo + base * 64;
    const __nv_bfloat16 *rh = g_relk_hi + (size_t)h * 1023 * 64;
    const __nv_bfloat16 *rlp = g_relk_lo + (size_t)h * 1023 * 64;
    int rbase = 448 - t0;

    auto fillChunk = [&](int ch) {
        int st = ch % 3;
        const __nv_bfloat16 *ph, *pl;
        int row0, rowmax;
        if (ch < 8)       { ph = kh; pl = klp; row0 = ch * 64; rowmax = 511; }
        else if (ch < 17) { ph = rh; pl = rlp; row0 = rbase + (ch - 8) * 64; rowmax = 1022; }
        else              { ph = vh; pl = vlp; row0 = (ch - 17) * 64; rowmax = 511; }
#pragma unroll
        for (int t = 0; t < 4; t++) {
            int i = tid + t * 256;
            int part = i >> 9, r = (i >> 3) & 63, cc = i & 7;
            int rr = row0 + r; if (rr > rowmax) rr = rowmax;
            const __nv_bfloat16* src = (part ? pl : ph) + (size_t)rr * 64 + cc * 8;
            cp_async16(sb + OFF_KV + st * 18432 + part * 9216 + r * 144 + cc * 16, src);
        }
        cp_commit();
    };

    fillChunk(0);
    fillChunk(1);

    // q prep: +bias (fp32), split -> qc hi/lo, qp hi/lo (stride 144B, bf16)
    {
        int r = tid >> 2, c0 = (tid & 3) << 4;
#pragma unroll
        for (int i = 0; i < 4; i++) {
            int cc = c0 + i * 4;
            float4 qv = *(const float4*)(qb + r * 64 + cc);
            float4 bc = *(const float4*)(rcb + h * 64 + cc);
            float4 bp = *(const float4*)(rpb + h * 64 + cc);
            uint32_t off = r * 144 + cc * 2;
            uint32_t lo, hi;
            hi = pack_split(qv.x + bc.x, qv.y + bc.y, lo);
            *(uint32_t*)(smb + OFF_QCH + off) = hi;        *(uint32_t*)(smb + OFF_QCH + 9216 + off) = lo;
            hi = pack_split(qv.z + bc.z, qv.w + bc.w, lo);
            *(uint32_t*)(smb + OFF_QCH + off + 4) = hi;    *(uint32_t*)(smb + OFF_QCH + 9216 + off + 4) = lo;
            hi = pack_split(qv.x + bp.x, qv.y + bp.y, lo);
            *(uint32_t*)(smb + OFF_QCH + 18432 + off) = hi;   *(uint32_t*)(smb + OFF_QCH + 27648 + off) = lo;
            hi = pack_split(qv.z + bp.z, qv.w + bp.w, lo);
            *(uint32_t*)(smb + OFF_QCH + 18432 + off + 4) = hi; *(uint32_t*)(smb + OFF_QCH + 27648 + off + 4) = lo;
        }
    }

    float o[2][2][4];
#pragma unroll
    for (int a = 0; a < 2; a++)
#pragma unroll
        for (int bq = 0; bq < 2; bq++)
#pragma unroll
            for (int q = 0; q < 4; q++) o[a][bq][q] = 0.f;

    for (int c = 0; c < 25; c++) {
        if (c < 24) cp_wait1(); else cp_wait0();
        __syncthreads();

        if (c <= 22) fillChunk(c + 2);

        if (c == 17) {
            // softmax + in-place P bf16 hi/lo conversion (blocked 32B layout)
            int r = tid >> 2, l4 = tid & 3;
            float* Sr = S + r * 516;
            float mx = -3.0e38f;
            for (int bq = l4; bq < 64; bq += 4) {
                float4 v0 = *(float4*)&Sr[bq * 8];
                float4 v1 = *(float4*)&Sr[bq * 8 + 4];
                mx = fmaxf(mx, fmaxf(fmaxf(v0.x, v0.y), fmaxf(v0.z, v0.w)));
                mx = fmaxf(mx, fmaxf(fmaxf(v1.x, v1.y), fmaxf(v1.z, v1.w)));
            }
            mx = fmaxf(mx, __shfl_xor_sync(0xffffffffu, mx, 1));
            mx = fmaxf(mx, __shfl_xor_sync(0xffffffffu, mx, 2));
            float sum = 0.f;
            for (int bq = l4; bq < 64; bq += 4) {
                float4 v0 = *(float4*)&Sr[bq * 8];
                float4 v1 = *(float4*)&Sr[bq * 8 + 4];
                float e0 = __expf(v0.x - mx), e1 = __expf(v0.y - mx);
                float e2 = __expf(v0.z - mx), e3 = __expf(v0.w - mx);
                float e4 = __expf(v1.x - mx), e5 = __expf(v1.y - mx);
                float e6 = __expf(v1.z - mx), e7 = __expf(v1.w - mx);
                sum += (e0 + e1 + e2 + e3) + (e4 + e5 + e6 + e7);
                uint32_t l0, l1, l2, l3;
                uint32_t h0 = pack_split(e0, e1, l0);
                uint32_t h1 = pack_split(e2, e3, l1);
                uint32_t h2 = pack_split(e4, e5, l2);
                uint32_t h3 = pack_split(e6, e7, l3);
                uint4 hv; hv.x = h0; hv.y = h1; hv.z = h2; hv.w = h3;
                uint4 lv; lv.x = l0; lv.y = l1; lv.z = l2; lv.w = l3;
                *(uint4*)((char*)Sr + bq * 32) = hv;
                *(uint4*)((char*)Sr + bq * 32 + 16) = lv;
            }
            sum += __shfl_xor_sync(0xffffffffu, sum, 1);
            sum += __shfl_xor_sync(0xffffffffu, sum, 2);
            if (l4 == 0) rs[r] = sum;
            __syncthreads();
        }

        uint32_t kvh = sb + OFF_KV + (c % 3) * 18432;
        uint32_t kvl = kvh + 9216;

        if (c < 17) {
            bool isRel = c >= 8;
            uint32_t qh = sb + OFF_QCH + (isRel ? 18432 : 0);
            uint32_t ql = qh + 9216;
            float acc[2][2][4];
#pragma unroll
            for (int a = 0; a < 2; a++)
#pragma unroll
                for (int bq = 0; bq < 2; bq++)
#pragma unroll
                    for (int q = 0; q < 4; q++) acc[a][bq][q] = 0.f;
#pragma unroll
            for (int ks = 0; ks < 4; ks++) {
                uint32_t aoff = (32 * wm + (lane & 15)) * 144 + ks * 32 + ((lane >> 4) << 4);
                uint32_t Ah0[4], Ah1[4], Al0[4], Al1[4], Bh[4], Bl[4];
                ldsm4(Ah0, qh + aoff); ldsm4(Ah1, qh + aoff + 2304);
                ldsm4(Al0, ql + aoff); ldsm4(Al1, ql + aoff + 2304);
                uint32_t boff = (16 * wn + ((lane >> 4) << 3) + (lane & 7)) * 144
                              + ks * 32 + ((lane & 8) << 1);
                ldsm4(Bh, kvh + boff); ldsm4(Bl, kvl + boff);
                mma16816(acc[0][0], Ah0, Bh[0], Bh[1]); mma16816(acc[0][1], Ah0, Bh[2], Bh[3]);
                mma16816(acc[1][0], Ah1, Bh[0], Bh[1]); mma16816(acc[1][1], Ah1, Bh[2], Bh[3]);
                mma16816(acc[0][0], Ah0, Bl[0], Bl[1]); mma16816(acc[0][1], Ah0, Bl[2], Bl[3]);
                mma16816(acc[1][0], Ah1, Bl[0], Bl[1]); mma16816(acc[1][1], Ah1, Bl[2], Bl[3]);
                mma16816(acc[0][0], Al0, Bh[0], Bh[1]); mma16816(acc[0][1], Al0, Bh[2], Bh[3]);
                mma16816(acc[1][0], Al1, Bh[0], Bh[1]); mma16816(acc[1][1], Al1, Bh[2], Bh[3]);
            }
            if (!isRel) {
                int scol = c * 64 + 16 * wn;
#pragma unroll
                for (int mt = 0; mt < 2; mt++) {
                    int t1 = 32 * wm + 16 * mt + (lane >> 2);
#pragma unroll
                    for (int nt = 0; nt < 2; nt++) {
                        int col = scol + 8 * nt + ((lane & 3) << 1);
                        S[t1 * 516 + col]           = acc[mt][nt][0] * 0.125f;
                        S[t1 * 516 + col + 1]       = acc[mt][nt][1] * 0.125f;
                        S[(t1 + 8) * 516 + col]     = acc[mt][nt][2] * 0.125f;
                        S[(t1 + 8) * 516 + col + 1] = acc[mt][nt][3] * 0.125f;
                    }
                }
            } else {
                int colb = (c - 8) * 64 + 16 * wn;
#pragma unroll
                for (int mt = 0; mt < 2; mt++) {
                    int t1 = 32 * wm + 16 * mt + (lane >> 2);
#pragma unroll
                    for (int nt = 0; nt < 2; nt++) {
                        int rl0 = colb + 8 * nt + ((lane & 3) << 1);
                        int s1 = rl0 + t1 - 63;
                        if (s1 >= 0 && s1 < 512)         S[t1 * 516 + s1]           += acc[mt][nt][0];
                        if (s1 + 1 >= 0 && s1 + 1 < 512) S[t1 * 516 + s1 + 1]       += acc[mt][nt][1];
                        int s2 = s1 + 8;
                        if (s2 >= 0 && s2 < 512)         S[(t1 + 8) * 516 + s2]     += acc[mt][nt][2];
                        if (s2 + 1 >= 0 && s2 + 1 < 512) S[(t1 + 8) * 516 + s2 + 1] += acc[mt][nt][3];
                    }
                }
            }
        } else {
            int cv = c - 17;
#pragma unroll
            for (int ks = 0; ks < 4; ks++) {
                uint32_t aoff = (32 * wm + (lane & 15)) * 2064 + cv * 256 + ks * 64
                              + ((lane >> 4) << 5);
                uint32_t Ph0[4], Ph1[4], Pl0[4], Pl1[4], Vh[4], Vl[4];
                ldsm4(Ph0, sb + aoff); ldsm4(Ph1, sb + aoff + 33024);
                ldsm4(Pl0, sb + aoff + 16); ldsm4(Pl1, sb + aoff + 33024 + 16);
                int g = lane >> 3;
                uint32_t boff = (ks * 16 + ((g & 1) << 3) + (lane & 7)) * 144
                              + 32 * wn + ((g >> 1) << 4);
                ldsm4t(Vh, kvh + boff); ldsm4t(Vl, kvl + boff);
                mma16816(o[0][0], Ph0, Vh[0], Vh[1]); mma16816(o[0][1], Ph0, Vh[2], Vh[3]);
                mma16816(o[1][0], Ph1, Vh[0], Vh[1]); mma16816(o[1][1], Ph1, Vh[2], Vh[3]);
                mma16816(o[0][0], Ph0, Vl[0], Vl[1]); mma16816(o[0][1], Ph0, Vl[2], Vl[3]);
                mma16816(o[1][0], Ph1, Vl[0], Vl[1]); mma16816(o[1][1], Ph1, Vl[2], Vl[3]);
                mma16816(o[0][0], Pl0, Vh[0], Vh[1]); mma16816(o[0][1], Pl0, Vh[2], Vh[3]);
                mma16816(o[1][0], Pl1, Vh[0], Vh[1]); mma16816(o[1][1], Pl1, Vh[2], Vh[3]);
            }
        }
    }

    // normalize + write fp16 hi/lo for out-proj (A operand of fp16 GEMM)
    int colc = 16 * wn;
#pragma unroll
    for (int mt = 0; mt < 2; mt++) {
        int t1 = 32 * wm + 16 * mt + (lane >> 2);
        float i1 = 1.f / rs[t1], i2 = 1.f / rs[t1 + 8];
        size_t row1 = (size_t)bN * 4096 + (size_t)w * 512 + t0 + t1;
#pragma unroll
        for (int nt = 0; nt < 2; nt++) {
            int col = colc + 8 * nt + ((lane & 3) << 1);
            size_t off1 = row1 * 768 + h * 64 + col;
            size_t off2 = (row1 + 8) * 768 + h * 64 + col;
            uint32_t lo, hi;
            hi = pack_splith(o[mt][nt][0] * i1, o[mt][nt][1] * i1, lo);
            *(uint32_t*)(g_att_hi + off1) = hi;
            *(uint32_t*)(g_att_lo + off1) = lo;
            hi = pack_splith(o[mt][nt][2] * i2, o[mt][nt][3] * i2, lo);
            *(uint32_t*)(g_att_hi + off2) = hi;
            *(uint32_t*)(g_att_lo + off2) = lo;
        }
    }
}

// ================= launch =================
extern "C" void kernel_launch(void* const* d_in, const int* in_sizes, int n_in,
                              void* d_out, int out_size)
{
    const float* x     = (const float*)d_in[0];
    const float* w_qkv = (const float*)d_in[1];
    const float* w_out = (const float*)d_in[2];
    const float* b_out = (const float*)d_in[3];
    const float* w_rel = (const float*)d_in[4];
    const float* rcb   = (const float*)d_in[5];
    const float* rpb   = (const float*)d_in[6];
    float* out = (float*)d_out;

    cudaFuncSetAttribute(attn_kernel, cudaFuncAttributeMaxDynamicSharedMemorySize, ATT_SMEM);
    cudaFuncSetAttribute(mma_gemm_merged, cudaFuncAttributeMaxDynamicSharedMemorySize, GEMM_SMEM);
    cudaFuncSetAttribute(mma_gemm_out, cudaFuncAttributeMaxDynamicSharedMemorySize, GEMM_SMEM);

    prep_kernel<<<5440, 256>>>(x, w_qkv, w_out, w_rel);
    mma_gemm_merged<<<1600, 256, GEMM_SMEM>>>();
    attn_kernel<<<1536, 256, ATT_SMEM>>>(rcb, rpb);
    mma_gemm_out<<<dim3(8, 64), 256, GEMM_SMEM>>>(b_out, out);
}

// round 14
// speedup vs baseline: 1.1880x; 1.1880x over previous
#include <cuda_runtime.h>
#include <cuda_bf16.h>
#include <cuda_fp16.h>
#include <math.h>
#include <stdint.h>

// ================= scratch (device globals) =================
__device__ float g_q[6291456];                         // [B*H][4096][64] fp32
__device__ __nv_bfloat16 g_k_hi[6291456], g_k_lo[6291456];      // attn operands (bf16)
__device__ __nv_bfloat16 g_v_hi[6291456], g_v_lo[6291456];
__device__ __nv_bfloat16 g_relk_hi[12 * 1023 * 64], g_relk_lo[12 * 1023 * 64];

__device__ __half g_x_hi[8192 * 768];                           // GEMM A operands (fp16 hi only)
__device__ __half g_wqkv_hi[2304 * 768], g_wqkv_lo[2304 * 768]; // [N][K] fp16 hi/lo
__device__ __half g_wout_hi[768 * 768],  g_wout_lo[768 * 768];
__device__ __half g_wrel_hi[768 * 768],  g_wrel_lo[768 * 768];
__device__ __half g_pos_hi[1024 * 768];                         // row 1023 stays zero
__device__ __half g_att_hi[8192 * 768];

// ================= helpers =================
__device__ __forceinline__ uint32_t smem_u32(const void* p) {
    uint32_t a;
    asm("{ .reg .u64 t; cvta.to.shared.u64 t, %1; cvt.u32.u64 %0, t; }" : "=r"(a) : "l"(p));
    return a;
}
__device__ __forceinline__ void cp_async16(uint32_t dst, const void* src) {
    asm volatile("cp.async.ca.shared.global [%0], [%1], 16;" :: "r"(dst), "l"(src));
}
__device__ __forceinline__ void cp_commit() { asm volatile("cp.async.commit_group;"); }
__device__ __forceinline__ void cp_wait1() { asm volatile("cp.async.wait_group 1;"); }
__device__ __forceinline__ void cp_wait0() { asm volatile("cp.async.wait_group 0;"); }

__device__ __forceinline__ void ldsm4(uint32_t* r, uint32_t addr) {
    asm volatile("ldmatrix.sync.aligned.m8n8.x4.shared.b16 {%0,%1,%2,%3}, [%4];"
                 : "=r"(r[0]), "=r"(r[1]), "=r"(r[2]), "=r"(r[3]) : "r"(addr));
}
__device__ __forceinline__ void ldsm4t(uint32_t* r, uint32_t addr) {
    asm volatile("ldmatrix.sync.aligned.m8n8.x4.trans.shared.b16 {%0,%1,%2,%3}, [%4];"
                 : "=r"(r[0]), "=r"(r[1]), "=r"(r[2]), "=r"(r[3]) : "r"(addr));
}
// bf16 MMA (attention path)
__device__ __forceinline__ void mma16816(float* d, const uint32_t* a, uint32_t b0, uint32_t b1) {
    asm volatile("mma.sync.aligned.m16n8k16.row.col.f32.bf16.bf16.f32 "
                 "{%0,%1,%2,%3}, {%4,%5,%6,%7}, {%8,%9}, {%0,%1,%2,%3};"
                 : "+f"(d[0]), "+f"(d[1]), "+f"(d[2]), "+f"(d[3])
                 : "r"(a[0]), "r"(a[1]), "r"(a[2]), "r"(a[3]), "r"(b0), "r"(b1));
}
// fp16 MMA with fp32 accumulate (GEMM)
__device__ __forceinline__ void mma_f16f32(float* d, const uint32_t* a, uint32_t b0, uint32_t b1) {
    asm volatile("mma.sync.aligned.m16n8k16.row.col.f32.f16.f16.f32 "
                 "{%0,%1,%2,%3}, {%4,%5,%6,%7}, {%8,%9}, {%0,%1,%2,%3};"
                 : "+f"(d[0]), "+f"(d[1]), "+f"(d[2]), "+f"(d[3])
                 : "r"(a[0]), "r"(a[1]), "r"(a[2]), "r"(a[3]), "r"(b0), "r"(b1));
}
__device__ __forceinline__ void split2(float v, __nv_bfloat16& h, __nv_bfloat16& l) {
    h = __float2bfloat16(v);
    l = __float2bfloat16(v - __bfloat162float(h));
}
__device__ __forceinline__ void split2h(float v, __half& h, __half& l) {
    h = __float2half_rn(v);
    l = __float2half_rn(v - __half2float(h));
}
// bf16 pack (attention P/Q smem path)
__device__ __forceinline__ uint32_t pack_split(float a, float b, uint32_t& lo) {
    uint32_t h;
    asm("cvt.rn.bf16x2.f32 %0, %1, %2;" : "=r"(h) : "f"(b), "f"(a));
    float ra = __uint_as_float(h << 16);
    float rb = __uint_as_float(h & 0xffff0000u);
    asm("cvt.rn.bf16x2.f32 %0, %1, %2;" : "=r"(lo) : "f"(b - rb), "f"(a - ra));
    return h;
}

// ================= kernel 1: merged prologue =================
__device__ __forceinline__ void splitT_body(const float* __restrict__ src,
                                            __half* __restrict__ hi,
                                            __half* __restrict__ lo,
                                            int K, int N, int bx, int by, int tid,
                                            float (*t)[33]) {
    int n0 = bx * 32, k0 = by * 32;
    int x = tid & 31, y0 = tid >> 5;
#pragma unroll
    for (int i = 0; i < 4; i++) {
        int y = y0 + i * 8;
        t[y][x] = src[(size_t)(k0 + y) * N + n0 + x];
    }
    __syncthreads();
#pragma unroll
    for (int i = 0; i < 4; i++) {
        int y = y0 + i * 8;
        float v = t[x][y];
        __half a, b;
        split2h(v, a, b);
        size_t o = (size_t)(n0 + y) * K + k0 + x;
        hi[o] = a; lo[o] = b;
    }
}

__global__ __launch_bounds__(256) void prep_kernel(
    const float* __restrict__ x, const float* __restrict__ w_qkv,
    const float* __restrict__ w_out, const float* __restrict__ w_rel)
{
    __shared__ float t[32][33];
    __shared__ double red[2][128];
    int bid = blockIdx.x, tid = threadIdx.x;

    if (bid < 2048) {
#pragma unroll
        for (int it = 0; it < 12; it++) {
            int i = (bid * 12 + it) * 256 + tid;
            g_x_hi[i] = __float2half_rn(x[i]);
        }
    } else if (bid < 3776) {
        int rid = bid - 2048;
        splitT_body(w_qkv, g_wqkv_hi, g_wqkv_lo, 768, 2304, rid % 72, rid / 72, tid, t);
    } else if (bid < 4352) {
        int rid = bid - 3776;
        splitT_body(w_out, g_wout_hi, g_wout_lo, 768, 768, rid % 24, rid / 24, tid, t);
    } else if (bid < 4928) {
        int rid = bid - 4352;
        splitT_body(w_rel, g_wrel_hi, g_wrel_lo, 768, 768, rid % 24, rid / 24, tid, t);
    } else {
        int half = tid >> 7, j = tid & 127;
        int r = (bid - 4928) * 2 + half;
        int rr = (r < 1023) ? r : 1022;
        float dist = (float)(rr - 511);
        double p = fabs((double)dist);

        double hl = exp2(3.0 + (double)j * (6.0 / 127.0));
        float ef = (float)exp(-0.6931471805599453 / hl * p);

        float cw = exp2f((float)(j + 1)) - 1.0f;
        float cm = (cw > (float)p) ? 1.0f : 0.0f;

        double mean = 4.0 * (double)(j + 1);
        double conc = (mean * 0.5) * (mean * 0.5);
        double rate = mean * 0.25;
        double lp = -rate * p - (lgamma(conc) - conc * log(rate));
        if (p > 0.0) lp += (conc - 1.0) * log(p);
        double prob = ((p > 0.0) ? exp(lp) : 0.0) + 1e-8;  // xlogy(c-1,0) -> -inf -> 0

        red[half][j] = prob;
        __syncthreads();
        for (int o = 64; o > 0; o >>= 1) {
            if (j < o) red[half][j] = fmax(red[half][j], red[half][j + o]);
            __syncthreads();
        }
        float gf = (float)(prob / red[half][0]);

        float sg = (dist > 0.f) ? 1.f : ((dist < 0.f) ? -1.f : 0.f);
        float vals[6] = {ef, cm, gf, sg * ef, sg * cm, sg * gf};
        if (r < 1023) {
            size_t base = (size_t)r * 768;
#pragma unroll
            for (int s = 0; s < 6; s++)
                g_pos_hi[base + s * 128 + j] = __float2half_rn(vals[s]);
        }
    }
}

// ================= fp16 2-product GEMM body (128x96 tile, 2 CTAs/SM) =================
// A·B ≈ Ah·Bh + Ah·Bl  (Al·Bh dropped: ~1.4e-4 rms rel error; Al never loaded)
#define APB 10240            // Ah: 128 rows x 80B
#define BPB 7680             // B part: 96 rows x 80B
#define STG 25600            // Ah + Bh + Bl
#define GEMM_SMEM (2 * STG)  // 51200
#define S_ST 100

__device__ __forceinline__ void mma_gemm_body(
    int bx, int by,
    const __half* __restrict__ Ah,
    const __half* __restrict__ Bh, const __half* __restrict__ Bl,
    const float* __restrict__ bias, float* __restrict__ Cout, int mode)
{
    extern __shared__ char dsm[];
    uint32_t sbase = smem_u32(dsm);
    int tid = threadIdx.x, wid = tid >> 5, lane = tid & 31;
    int wm = wid & 3, wn = wid >> 2;

    size_t m0 = (size_t)by * 128;
    int n0 = bx * 96;

    float acc[2][6][4];
#pragma unroll
    for (int i = 0; i < 2; i++)
#pragma unroll
        for (int j = 0; j < 6; j++)
#pragma unroll
            for (int q = 0; q < 4; q++) acc[i][j][q] = 0.f;

    int a_lr = lane & 15;
    int a_lc = (lane >> 4) << 3;
    int b_ln = ((lane >> 4) << 3) + (lane & 7);
    int b_lk = lane & 8;

    auto fill = [&](int s, int c) {
        uint32_t st = sbase + s * STG;
        int k0 = c * 32;
#pragma unroll
        for (int ii = 0; ii < 5; ii++) {
            int i = tid + ii * 256;          // 0..1279
            if (i < 512) {
                int rr = i >> 2, cc = i & 3;
                cp_async16(st + rr * 80 + cc * 16, Ah + (m0 + rr) * 768 + k0 + cc * 8);
            } else {
                int j = i - 512;             // 0..767
                int part = j >= 384; int jj = j - (part ? 384 : 0);
                int rr = jj >> 2, cc = jj & 3;
                const __half* src = (part ? Bl : Bh) + (size_t)(n0 + rr) * 768 + k0 + cc * 8;
                cp_async16(st + APB + part * BPB + rr * 80 + cc * 16, src);
            }
        }
        cp_commit();
    };

    fill(0, 0);
    for (int c = 0; c < 24; c++) {
        if (c < 23) { fill((c + 1) & 1, c + 1); cp_wait1(); } else { cp_wait0(); }
        __syncthreads();

        uint32_t st = sbase + (c & 1) * STG;
#pragma unroll
        for (int step = 0; step < 2; step++) {
            uint32_t ab = st + (wm * 32 + a_lr) * 80 + (step * 16 + a_lc) * 2;
            uint32_t bb = st + APB + (wn * 48 + b_ln) * 80 + (step * 16 + b_lk) * 2;
            uint32_t Af[2][4], Bf[3][4], Blf[3][4];
            ldsm4(Af[0], ab); ldsm4(Af[1], ab + 1280);
#pragma unroll
            for (int ng = 0; ng < 3; ng++) {
                ldsm4(Bf[ng],  bb + ng * 1280);
                ldsm4(Blf[ng], bb + BPB + ng * 1280);
            }
            // product 0: Ah*Bh
#pragma unroll
            for (int mi = 0; mi < 2; mi++)
#pragma unroll
                for (int ng = 0; ng < 3; ng++) {
                    mma_f16f32(acc[mi][ng * 2 + 0], Af[mi], Bf[ng][0], Bf[ng][1]);
                    mma_f16f32(acc[mi][ng * 2 + 1], Af[mi], Bf[ng][2], Bf[ng][3]);
                }
            // product 1: Ah*Bl
#pragma unroll
            for (int mi = 0; mi < 2; mi++)
#pragma unroll
                for (int ng = 0; ng < 3; ng++) {
                    mma_f16f32(acc[mi][ng * 2 + 0], Af[mi], Blf[ng][0], Blf[ng][1]);
                    mma_f16f32(acc[mi][ng * 2 + 1], Af[mi], Blf[ng][2], Blf[ng][3]);
                }
        }
        __syncthreads();
    }

    // stage accumulators to smem S[128][100]
    float* S = (float*)dsm;
#pragma unroll
    for (int mi = 0; mi < 2; mi++)
#pragma unroll
        for (int nj = 0; nj < 6; nj++) {
            int row = wm * 32 + mi * 16 + (lane >> 2);
            int col = wn * 48 + nj * 8 + (lane & 3) * 2;
            S[row * S_ST + col]             = acc[mi][nj][0];
            S[row * S_ST + col + 1]         = acc[mi][nj][1];
            S[(row + 8) * S_ST + col]       = acc[mi][nj][2];
            S[(row + 8) * S_ST + col + 1]   = acc[mi][nj][3];
        }
    __syncthreads();

    if (mode == 0) {
        int hh = bx >> 1;
        int dbase = (bx & 1) * 32;
        int bi = (int)(m0 >> 12);
        int nn0 = (int)(m0 & 4095);
        size_t ob = ((size_t)(bi * 12 + hh) * 4096 + nn0) * 64 + dbase;
        for (int task = wid; task < 384; task += 8) {
            int mm = task / 3;
            int which = task - 3 * mm;
            float v = S[mm * S_ST + 3 * lane + which];
            size_t o = ob + (size_t)mm * 64 + lane;
            if (which == 0) g_q[o] = v;
            else {
                __nv_bfloat16 hv, lv; split2(v, hv, lv);
                if (which == 1) { g_k_hi[o] = hv; g_k_lo[o] = lv; }
                else            { g_v_hi[o] = hv; g_v_lo[o] = lv; }
            }
        }
    } else if (mode == 1) {
        for (int task = wid; task < 384; task += 8) {
            int mm = task / 3;
            int g = task - 3 * mm;
            int cgl = n0 + g * 32 + lane;
            int hh = cgl >> 6, d = cgl & 63;
            int r = (int)m0 + mm;
            if (r < 1023) {
                __nv_bfloat16 hv, lv; split2(S[mm * S_ST + g * 32 + lane], hv, lv);
                size_t o = ((size_t)hh * 1023 + r) * 64 + d;
                g_relk_hi[o] = hv; g_relk_lo[o] = lv;
            }
        }
    } else {
        for (int task = wid; task < 384; task += 8) {
            int mm = task / 3;
            int g = task - 3 * mm;
            int j = g * 32 + lane;
            Cout[(m0 + mm) * 768 + n0 + j] = S[mm * S_ST + j] + bias[n0 + j];
        }
    }
}

// merged QKV (1536 blocks) + relk (64 blocks), 1D grid of 1600
__global__ __launch_bounds__(256, 2) void mma_gemm_merged() {
    int bid = blockIdx.x;
    if (bid < 1536)
        mma_gemm_body(bid % 24, bid / 24, g_x_hi, g_wqkv_hi, g_wqkv_lo,
                      nullptr, nullptr, 0);
    else {
        int rid = bid - 1536;
        mma_gemm_body(rid % 8, rid / 8, g_pos_hi, g_wrel_hi, g_wrel_lo,
                      nullptr, nullptr, 1);
    }
}

// out-proj
__global__ __launch_bounds__(256, 2) void mma_gemm_out(const float* __restrict__ bias,
                                                       float* __restrict__ Cout) {
    mma_gemm_body(blockIdx.x, blockIdx.y, g_att_hi, g_wout_hi, g_wout_lo,
                  bias, Cout, 2);
}

// ================= kernel 3: tensor-core fused window attention (bf16x3, unchanged) =================
#define OFF_QCH 132096
#define OFF_KV  168960
#define OFF_RS  224256
#define ATT_SMEM 224512

__global__ __launch_bounds__(256) void attn_kernel(const float* __restrict__ rcb,
                                                   const float* __restrict__ rpb)
{
    extern __shared__ char smb[];
    float* S = (float*)smb;
    float* rs = (float*)(smb + OFF_RS);
    uint32_t sb = smem_u32(smb);
    int tid = threadIdx.x, wid = tid >> 5, lane = tid & 31;
    int wm = wid & 1, wn = wid >> 1;

    int tt = blockIdx.x & 7, win = blockIdx.x >> 3;
    int bN = win / 96, rem = win - bN * 96, h = rem >> 3, w = rem & 7;
    int t0 = tt << 6;
    size_t base = ((size_t)(bN * 12 + h)) * 4096 + (size_t)w * 512;
    const float* qb = g_q + (base + t0) * 64;
    const __nv_bfloat16 *kh = g_k_hi + base * 64, *klp = g_k_lo + base * 64;
    const __nv_bfloat16 *vh = g_v_hi + base * 64, *vlp = g_v_lo + base * 64;
    const __nv_bfloat16 *rh = g_relk_hi + (size_t)h * 1023 * 64;
    const __nv_bfloat16 *rlp = g_relk_lo + (size_t)h * 1023 * 64;
    int rbase = 448 - t0;

    auto fillChunk = [&](int ch) {
        int st = ch % 3;
        const __nv_bfloat16 *ph, *pl;
        int row0, rowmax;
        if (ch < 8)       { ph = kh; pl = klp; row0 = ch * 64; rowmax = 511; }
        else if (ch < 17) { ph = rh; pl = rlp; row0 = rbase + (ch - 8) * 64; rowmax = 1022; }
        else              { ph = vh; pl = vlp; row0 = (ch - 17) * 64; rowmax = 511; }
#pragma unroll
        for (int t = 0; t < 4; t++) {
            int i = tid + t * 256;
            int part = i >> 9, r = (i >> 3) & 63, cc = i & 7;
            int rr = row0 + r; if (rr > rowmax) rr = rowmax;
            const __nv_bfloat16* src = (part ? pl : ph) + (size_t)rr * 64 + cc * 8;
            cp_async16(sb + OFF_KV + st * 18432 + part * 9216 + r * 144 + cc * 16, src);
        }
        cp_commit();
    };

    fillChunk(0);
    fillChunk(1);

    // q prep: +bias (fp32), split -> qc hi/lo, qp hi/lo (stride 144B, bf16)
    {
        int r = tid >> 2, c0 = (tid & 3) << 4;
#pragma unroll
        for (int i = 0; i < 4; i++) {
            int cc = c0 + i * 4;
            float4 qv = *(const float4*)(qb + r * 64 + cc);
            float4 bc = *(const float4*)(rcb + h * 64 + cc);
            float4 bp = *(const float4*)(rpb + h * 64 + cc);
            uint32_t off = r * 144 + cc * 2;
            uint32_t lo, hi;
            hi = pack_split(qv.x + bc.x, qv.y + bc.y, lo);
            *(uint32_t*)(smb + OFF_QCH + off) = hi;        *(uint32_t*)(smb + OFF_QCH + 9216 + off) = lo;
            hi = pack_split(qv.z + bc.z, qv.w + bc.w, lo);
            *(uint32_t*)(smb + OFF_QCH + off + 4) = hi;    *(uint32_t*)(smb + OFF_QCH + 9216 + off + 4) = lo;
            hi = pack_split(qv.x + bp.x, qv.y + bp.y, lo);
            *(uint32_t*)(smb + OFF_QCH + 18432 + off) = hi;   *(uint32_t*)(smb + OFF_QCH + 27648 + off) = lo;
            hi = pack_split(qv.z + bp.z, qv.w + bp.w, lo);
            *(uint32_t*)(smb + OFF_QCH + 18432 + off + 4) = hi; *(uint32_t*)(smb + OFF_QCH + 27648 + off + 4) = lo;
        }
    }

    float o[2][2][4];
#pragma unroll
    for (int a = 0; a < 2; a++)
#pragma unroll
        for (int bq = 0; bq < 2; bq++)
#pragma unroll
            for (int q = 0; q < 4; q++) o[a][bq][q] = 0.f;

    for (int c = 0; c < 25; c++) {
        if (c < 24) cp_wait1(); else cp_wait0();
        __syncthreads();

        if (c <= 22) fillChunk(c + 2);

        if (c == 17) {
            // softmax + in-place P bf16 hi/lo conversion (blocked 32B layout)
            int r = tid >> 2, l4 = tid & 3;
            float* Sr = S + r * 516;
            float mx = -3.0e38f;
            for (int bq = l4; bq < 64; bq += 4) {
                float4 v0 = *(float4*)&Sr[bq * 8];
                float4 v1 = *(float4*)&Sr[bq * 8 + 4];
                mx = fmaxf(mx, fmaxf(fmaxf(v0.x, v0.y), fmaxf(v0.z, v0.w)));
                mx = fmaxf(mx, fmaxf(fmaxf(v1.x, v1.y), fmaxf(v1.z, v1.w)));
            }
            mx = fmaxf(mx, __shfl_xor_sync(0xffffffffu, mx, 1));
            mx = fmaxf(mx, __shfl_xor_sync(0xffffffffu, mx, 2));
            float sum = 0.f;
            for (int bq = l4; bq < 64; bq += 4) {
                float4 v0 = *(float4*)&Sr[bq * 8];
                float4 v1 = *(float4*)&Sr[bq * 8 + 4];
                float e0 = __expf(v0.x - mx), e1 = __expf(v0.y - mx);
                float e2 = __expf(v0.z - mx), e3 = __expf(v0.w - mx);
                float e4 = __expf(v1.x - mx), e5 = __expf(v1.y - mx);
                float e6 = __expf(v1.z - mx), e7 = __expf(v1.w - mx);
                sum += (e0 + e1 + e2 + e3) + (e4 + e5 + e6 + e7);
                uint32_t l0, l1, l2, l3;
                uint32_t h0 = pack_split(e0, e1, l0);
                uint32_t h1 = pack_split(e2, e3, l1);
                uint32_t h2 = pack_split(e4, e5, l2);
                uint32_t h3 = pack_split(e6, e7, l3);
                uint4 hv; hv.x = h0; hv.y = h1; hv.z = h2; hv.w = h3;
                uint4 lv; lv.x = l0; lv.y = l1; lv.z = l2; lv.w = l3;
                *(uint4*)((char*)Sr + bq * 32) = hv;
                *(uint4*)((char*)Sr + bq * 32 + 16) = lv;
            }
            sum += __shfl_xor_sync(0xffffffffu, sum, 1);
            sum += __shfl_xor_sync(0xffffffffu, sum, 2);
            if (l4 == 0) rs[r] = sum;
            __syncthreads();
        }

        uint32_t kvh = sb + OFF_KV + (c % 3) * 18432;
        uint32_t kvl = kvh + 9216;

        if (c < 17) {
            bool isRel = c >= 8;
            uint32_t qh = sb + OFF_QCH + (isRel ? 18432 : 0);
            uint32_t ql = qh + 9216;
            float acc[2][2][4];
#pragma unroll
            for (int a = 0; a < 2; a++)
#pragma unroll
                for (int bq = 0; bq < 2; bq++)
#pragma unroll
                    for (int q = 0; q < 4; q++) acc[a][bq][q] = 0.f;
#pragma unroll
            for (int ks = 0; ks < 4; ks++) {
                uint32_t aoff = (32 * wm + (lane & 15)) * 144 + ks * 32 + ((lane >> 4) << 4);
                uint32_t Ah0[4], Ah1[4], Al0[4], Al1[4], Bh[4], Bl[4];
                ldsm4(Ah0, qh + aoff); ldsm4(Ah1, qh + aoff + 2304);
                ldsm4(Al0, ql + aoff); ldsm4(Al1, ql + aoff + 2304);
                uint32_t boff = (16 * wn + ((lane >> 4) << 3) + (lane & 7)) * 144
                              + ks * 32 + ((lane & 8) << 1);
                ldsm4(Bh, kvh + boff); ldsm4(Bl, kvl + boff);
                mma16816(acc[0][0], Ah0, Bh[0], Bh[1]); mma16816(acc[0][1], Ah0, Bh[2], Bh[3]);
                mma16816(acc[1][0], Ah1, Bh[0], Bh[1]); mma16816(acc[1][1], Ah1, Bh[2], Bh[3]);
                mma16816(acc[0][0], Ah0, Bl[0], Bl[1]); mma16816(acc[0][1], Ah0, Bl[2], Bl[3]);
                mma16816(acc[1][0], Ah1, Bl[0], Bl[1]); mma16816(acc[1][1], Ah1, Bl[2], Bl[3]);
                mma16816(acc[0][0], Al0, Bh[0], Bh[1]); mma16816(acc[0][1], Al0, Bh[2], Bh[3]);
                mma16816(acc[1][0], Al1, Bh[0], Bh[1]); mma16816(acc[1][1], Al1, Bh[2], Bh[3]);
            }
            if (!isRel) {
                int scol = c * 64 + 16 * wn;
#pragma unroll
                for (int mt = 0; mt < 2; mt++) {
                    int t1 = 32 * wm + 16 * mt + (lane >> 2);
#pragma unroll
                    for (int nt = 0; nt < 2; nt++) {
                        int col = scol + 8 * nt + ((lane & 3) << 1);
                        S[t1 * 516 + col]           = acc[mt][nt][0] * 0.125f;
                        S[t1 * 516 + col + 1]       = acc[mt][nt][1] * 0.125f;
                        S[(t1 + 8) * 516 + col]     = acc[mt][nt][2] * 0.125f;
                        S[(t1 + 8) * 516 + col + 1] = acc[mt][nt][3] * 0.125f;
                    }
                }
            } else {
                int colb = (c - 8) * 64 + 16 * wn;
#pragma unroll
                for (int mt = 0; mt < 2; mt++) {
                    int t1 = 32 * wm + 16 * mt + (lane >> 2);
#pragma unroll
                    for (int nt = 0; nt < 2; nt++) {
                        int rl0 = colb + 8 * nt + ((lane & 3) << 1);
                        int s1 = rl0 + t1 - 63;
                        if (s1 >= 0 && s1 < 512)         S[t1 * 516 + s1]           += acc[mt][nt][0];
                        if (s1 + 1 >= 0 && s1 + 1 < 512) S[t1 * 516 + s1 + 1]       += acc[mt][nt][1];
                        int s2 = s1 + 8;
                        if (s2 >= 0 && s2 < 512)         S[(t1 + 8) * 516 + s2]     += acc[mt][nt][2];
                        if (s2 + 1 >= 0 && s2 + 1 < 512) S[(t1 + 8) * 516 + s2 + 1] += acc[mt][nt][3];
                    }
                }
            }
        } else {
            int cv = c - 17;
#pragma unroll
            for (int ks = 0; ks < 4; ks++) {
                uint32_t aoff = (32 * wm + (lane & 15)) * 2064 + cv * 256 + ks * 64
                              + ((lane >> 4) << 5);
                uint32_t Ph0[4], Ph1[4], Pl0[4], Pl1[4], Vh[4], Vl[4];
                ldsm4(Ph0, sb + aoff); ldsm4(Ph1, sb + aoff + 33024);
                ldsm4(Pl0, sb + aoff + 16); ldsm4(Pl1, sb + aoff + 33024 + 16);
                int g = lane >> 3;
                uint32_t boff = (ks * 16 + ((g & 1) << 3) + (lane & 7)) * 144
                              + 32 * wn + ((g >> 1) << 4);
                ldsm4t(Vh, kvh + boff); ldsm4t(Vl, kvl + boff);
                mma16816(o[0][0], Ph0, Vh[0], Vh[1]); mma16816(o[0][1], Ph0, Vh[2], Vh[3]);
                mma16816(o[1][0], Ph1, Vh[0], Vh[1]); mma16816(o[1][1], Ph1, Vh[2], Vh[3]);
                mma16816(o[0][0], Ph0, Vl[0], Vl[1]); mma16816(o[0][1], Ph0, Vl[2], Vl[3]);
                mma16816(o[1][0], Ph1, Vl[0], Vl[1]); mma16816(o[1][1], Ph1, Vl[2], Vl[3]);
                mma16816(o[0][0], Pl0, Vh[0], Vh[1]); mma16816(o[0][1], Pl0, Vh[2], Vh[3]);
                mma16816(o[1][0], Pl1, Vh[0], Vh[1]); mma16816(o[1][1], Pl1, Vh[2], Vh[3]);
            }
        }
    }

    // normalize + write fp16 hi (A operand of 2-product out-proj GEMM)
    int colc = 16 * wn;
#pragma unroll
    for (int mt = 0; mt < 2; mt++) {
        int t1 = 32 * wm + 16 * mt + (lane >> 2);
        float i1 = 1.f / rs[t1], i2 = 1.f / rs[t1 + 8];
        size_t row1 = (size_t)bN * 4096 + (size_t)w * 512 + t0 + t1;
#pragma unroll
        for (int nt = 0; nt < 2; nt++) {
            int col = colc + 8 * nt + ((lane & 3) << 1);
            size_t off1 = row1 * 768 + h * 64 + col;
            size_t off2 = (row1 + 8) * 768 + h * 64 + col;
            __half2 hv1 = __floats2half2_rn(o[mt][nt][0] * i1, o[mt][nt][1] * i1);
            __half2 hv2 = __floats2half2_rn(o[mt][nt][2] * i2, o[mt][nt][3] * i2);
            *(__half2*)(g_att_hi + off1) = hv1;
            *(__half2*)(g_att_hi + off2) = hv2;
        }
    }
}

// ================= launch =================
extern "C" void kernel_launch(void* const* d_in, const int* in_sizes, int n_in,
                              void* d_out, int out_size)
{
    const float* x     = (const float*)d_in[0];
    const float* w_qkv = (const float*)d_in[1];
    const float* w_out = (const float*)d_in[2];
    const float* b_out = (const float*)d_in[3];
    const float* w_rel = (const float*)d_in[4];
    const float* rcb   = (const float*)d_in[5];
    const float* rpb   = (const float*)d_in[6];
    float* out = (float*)d_out;

    cudaFuncSetAttribute(attn_kernel, cudaFuncAttributeMaxDynamicSharedMemorySize, ATT_SMEM);
    cudaFuncSetAttribute(mma_gemm_merged, cudaFuncAttributeMaxDynamicSharedMemorySize, GEMM_SMEM);
    cudaFuncSetAttribute(mma_gemm_out, cudaFuncAttributeMaxDynamicSharedMemorySize, GEMM_SMEM);

    prep_kernel<<<5440, 256>>>(x, w_qkv, w_out, w_rel);
    mma_gemm_merged<<<1600, 256, GEMM_SMEM>>>();
    attn_kernel<<<1536, 256, ATT_SMEM>>>(rcb, rpb);
    mma_gemm_out<<<dim3(8, 64), 256, GEMM_SMEM>>>(b_out, out);
}

// round 16
// speedup vs baseline: 1.2922x; 1.0877x over previous
#include <cuda_runtime.h>
#include <cuda_fp16.h>
#include <math.h>
#include <stdint.h>

// ================= scratch (device globals) =================
__device__ float g_q[6291456];                         // [B*H][4096][64] fp32
__device__ __half g_k_hi[6291456], g_k_lo[6291456];    // attn operands (fp16)
__device__ __half g_v_hi[6291456], g_v_lo[6291456];
__device__ __half g_relk_hi[12 * 1023 * 64], g_relk_lo[12 * 1023 * 64];

__device__ __half g_x_hi[8192 * 768];                           // GEMM A operands (fp16 hi only)
__device__ __half g_wqkv_hi[2304 * 768], g_wqkv_lo[2304 * 768]; // [N][K] fp16 hi/lo
__device__ __half g_wout_hi[768 * 768],  g_wout_lo[768 * 768];
__device__ __half g_wrel_hi[768 * 768],  g_wrel_lo[768 * 768];
__device__ __half g_pos_hi[1024 * 768];                         // row 1023 stays zero
__device__ __half g_att_hi[8192 * 768];

// ================= helpers =================
__device__ __forceinline__ uint32_t smem_u32(const void* p) {
    uint32_t a;
    asm("{ .reg .u64 t; cvta.to.shared.u64 t, %1; cvt.u32.u64 %0, t; }" : "=r"(a) : "l"(p));
    return a;
}
__device__ __forceinline__ void cp_async16(uint32_t dst, const void* src) {
    asm volatile("cp.async.ca.shared.global [%0], [%1], 16;" :: "r"(dst), "l"(src));
}
__device__ __forceinline__ void cp_commit() { asm volatile("cp.async.commit_group;"); }
__device__ __forceinline__ void cp_wait1() { asm volatile("cp.async.wait_group 1;"); }
__device__ __forceinline__ void cp_wait0() { asm volatile("cp.async.wait_group 0;"); }

__device__ __forceinline__ void ldsm4(uint32_t* r, uint32_t addr) {
    asm volatile("ldmatrix.sync.aligned.m8n8.x4.shared.b16 {%0,%1,%2,%3}, [%4];"
                 : "=r"(r[0]), "=r"(r[1]), "=r"(r[2]), "=r"(r[3]) : "r"(addr));
}
__device__ __forceinline__ void ldsm4t(uint32_t* r, uint32_t addr) {
    asm volatile("ldmatrix.sync.aligned.m8n8.x4.trans.shared.b16 {%0,%1,%2,%3}, [%4];"
                 : "=r"(r[0]), "=r"(r[1]), "=r"(r[2]), "=r"(r[3]) : "r"(addr));
}
// fp16 MMA with fp32 accumulate
__device__ __forceinline__ void mma_f16f32(float* d, const uint32_t* a, uint32_t b0, uint32_t b1) {
    asm volatile("mma.sync.aligned.m16n8k16.row.col.f32.f16.f16.f32 "
                 "{%0,%1,%2,%3}, {%4,%5,%6,%7}, {%8,%9}, {%0,%1,%2,%3};"
                 : "+f"(d[0]), "+f"(d[1]), "+f"(d[2]), "+f"(d[3])
                 : "r"(a[0]), "r"(a[1]), "r"(a[2]), "r"(a[3]), "r"(b0), "r"(b1));
}
__device__ __forceinline__ void split2h(float v, __half& h, __half& l) {
    h = __float2half_rn(v);
    l = __float2half_rn(v - __half2float(h));
}
// fp16 pack hi+lo
__device__ __forceinline__ uint32_t pack_splith(float a, float b, uint32_t& lo) {
    __half2 h = __floats2half2_rn(a, b);
    float ra = __half2float(__low2half(h));
    float rb = __half2float(__high2half(h));
    __half2 l = __floats2half2_rn(a - ra, b - rb);
    lo = *(uint32_t*)&l;
    return *(uint32_t*)&h;
}
__device__ __forceinline__ uint32_t pack2h(float a, float b) {
    __half2 h = __floats2half2_rn(a, b);
    return *(uint32_t*)&h;
}

// ================= kernel 1: merged prologue =================
__device__ __forceinline__ void splitT_body(const float* __restrict__ src,
                                            __half* __restrict__ hi,
                                            __half* __restrict__ lo,
                                            int K, int N, int bx, int by, int tid,
                                            float (*t)[33]) {
    int n0 = bx * 32, k0 = by * 32;
    int x = tid & 31, y0 = tid >> 5;
#pragma unroll
    for (int i = 0; i < 4; i++) {
        int y = y0 + i * 8;
        t[y][x] = src[(size_t)(k0 + y) * N + n0 + x];
    }
    __syncthreads();
#pragma unroll
    for (int i = 0; i < 4; i++) {
        int y = y0 + i * 8;
        float v = t[x][y];
        __half a, b;
        split2h(v, a, b);
        size_t o = (size_t)(n0 + y) * K + k0 + x;
        hi[o] = a; lo[o] = b;
    }
}

__global__ __launch_bounds__(256) void prep_kernel(
    const float* __restrict__ x, const float* __restrict__ w_qkv,
    const float* __restrict__ w_out, const float* __restrict__ w_rel)
{
    __shared__ float t[32][33];
    __shared__ double red[2][128];
    int bid = blockIdx.x, tid = threadIdx.x;

    if (bid < 2048) {
#pragma unroll
        for (int it = 0; it < 12; it++) {
            int i = (bid * 12 + it) * 256 + tid;
            g_x_hi[i] = __float2half_rn(x[i]);
        }
    } else if (bid < 3776) {
        int rid = bid - 2048;
        splitT_body(w_qkv, g_wqkv_hi, g_wqkv_lo, 768, 2304, rid % 72, rid / 72, tid, t);
    } else if (bid < 4352) {
        int rid = bid - 3776;
        splitT_body(w_out, g_wout_hi, g_wout_lo, 768, 768, rid % 24, rid / 24, tid, t);
    } else if (bid < 4928) {
        int rid = bid - 4352;
        splitT_body(w_rel, g_wrel_hi, g_wrel_lo, 768, 768, rid % 24, rid / 24, tid, t);
    } else {
        int half = tid >> 7, j = tid & 127;
        int r = (bid - 4928) * 2 + half;
        int rr = (r < 1023) ? r : 1022;
        float dist = (float)(rr - 511);
        double p = fabs((double)dist);

        double hl = exp2(3.0 + (double)j * (6.0 / 127.0));
        float ef = (float)exp(-0.6931471805599453 / hl * p);

        float cw = exp2f((float)(j + 1)) - 1.0f;
        float cm = (cw > (float)p) ? 1.0f : 0.0f;

        double mean = 4.0 * (double)(j + 1);
        double conc = (mean * 0.5) * (mean * 0.5);
        double rate = mean * 0.25;
        double lp = -rate * p - (lgamma(conc) - conc * log(rate));
        if (p > 0.0) lp += (conc - 1.0) * log(p);
        double prob = ((p > 0.0) ? exp(lp) : 0.0) + 1e-8;  // xlogy(c-1,0) -> -inf -> 0

        red[half][j] = prob;
        __syncthreads();
        for (int o = 64; o > 0; o >>= 1) {
            if (j < o) red[half][j] = fmax(red[half][j], red[half][j + o]);
            __syncthreads();
        }
        float gf = (float)(prob / red[half][0]);

        float sg = (dist > 0.f) ? 1.f : ((dist < 0.f) ? -1.f : 0.f);
        float vals[6] = {ef, cm, gf, sg * ef, sg * cm, sg * gf};
        if (r < 1023) {
            size_t base = (size_t)r * 768;
#pragma unroll
            for (int s = 0; s < 6; s++)
                g_pos_hi[base + s * 128 + j] = __float2half_rn(vals[s]);
        }
    }
}

// ================= fp16 2-product GEMM body (128x96 tile, 2 CTAs/SM) =================
#define APB 10240
#define BPB 7680
#define STG 25600
#define GEMM_SMEM (2 * STG)
#define S_ST 100

__device__ __forceinline__ void mma_gemm_body(
    int bx, int by,
    const __half* __restrict__ Ah,
    const __half* __restrict__ Bh, const __half* __restrict__ Bl,
    const float* __restrict__ bias, float* __restrict__ Cout, int mode)
{
    extern __shared__ char dsm[];
    uint32_t sbase = smem_u32(dsm);
    int tid = threadIdx.x, wid = tid >> 5, lane = tid & 31;
    int wm = wid & 3, wn = wid >> 2;

    size_t m0 = (size_t)by * 128;
    int n0 = bx * 96;

    float acc[2][6][4];
#pragma unroll
    for (int i = 0; i < 2; i++)
#pragma unroll
        for (int j = 0; j < 6; j++)
#pragma unroll
            for (int q = 0; q < 4; q++) acc[i][j][q] = 0.f;

    int a_lr = lane & 15;
    int a_lc = (lane >> 4) << 3;
    int b_ln = ((lane >> 4) << 3) + (lane & 7);
    int b_lk = lane & 8;

    auto fill = [&](int s, int c) {
        uint32_t st = sbase + s * STG;
        int k0 = c * 32;
#pragma unroll
        for (int ii = 0; ii < 5; ii++) {
            int i = tid + ii * 256;
            if (i < 512) {
                int rr = i >> 2, cc = i & 3;
                cp_async16(st + rr * 80 + cc * 16, Ah + (m0 + rr) * 768 + k0 + cc * 8);
            } else {
                int j = i - 512;
                int part = j >= 384; int jj = j - (part ? 384 : 0);
                int rr = jj >> 2, cc = jj & 3;
                const __half* src = (part ? Bl : Bh) + (size_t)(n0 + rr) * 768 + k0 + cc * 8;
                cp_async16(st + APB + part * BPB + rr * 80 + cc * 16, src);
            }
        }
        cp_commit();
    };

    fill(0, 0);
    for (int c = 0; c < 24; c++) {
        if (c < 23) { fill((c + 1) & 1, c + 1); cp_wait1(); } else { cp_wait0(); }
        __syncthreads();

        uint32_t st = sbase + (c & 1) * STG;
#pragma unroll
        for (int step = 0; step < 2; step++) {
            uint32_t ab = st + (wm * 32 + a_lr) * 80 + (step * 16 + a_lc) * 2;
            uint32_t bb = st + APB + (wn * 48 + b_ln) * 80 + (step * 16 + b_lk) * 2;
            uint32_t Af[2][4], Bf[3][4], Blf[3][4];
            ldsm4(Af[0], ab); ldsm4(Af[1], ab + 1280);
#pragma unroll
            for (int ng = 0; ng < 3; ng++) {
                ldsm4(Bf[ng],  bb + ng * 1280);
                ldsm4(Blf[ng], bb + BPB + ng * 1280);
            }
#pragma unroll
            for (int mi = 0; mi < 2; mi++)
#pragma unroll
                for (int ng = 0; ng < 3; ng++) {
                    mma_f16f32(acc[mi][ng * 2 + 0], Af[mi], Bf[ng][0], Bf[ng][1]);
                    mma_f16f32(acc[mi][ng * 2 + 1], Af[mi], Bf[ng][2], Bf[ng][3]);
                }
#pragma unroll
            for (int mi = 0; mi < 2; mi++)
#pragma unroll
                for (int ng = 0; ng < 3; ng++) {
                    mma_f16f32(acc[mi][ng * 2 + 0], Af[mi], Blf[ng][0], Blf[ng][1]);
                    mma_f16f32(acc[mi][ng * 2 + 1], Af[mi], Blf[ng][2], Blf[ng][3]);
                }
        }
        __syncthreads();
    }

    float* S = (float*)dsm;
#pragma unroll
    for (int mi = 0; mi < 2; mi++)
#pragma unroll
        for (int nj = 0; nj < 6; nj++) {
            int row = wm * 32 + mi * 16 + (lane >> 2);
            int col = wn * 48 + nj * 8 + (lane & 3) * 2;
            S[row * S_ST + col]             = acc[mi][nj][0];
            S[row * S_ST + col + 1]         = acc[mi][nj][1];
            S[(row + 8) * S_ST + col]       = acc[mi][nj][2];
            S[(row + 8) * S_ST + col + 1]   = acc[mi][nj][3];
        }
    __syncthreads();

    if (mode == 0) {
        int hh = bx >> 1;
        int dbase = (bx & 1) * 32;
        int bi = (int)(m0 >> 12);
        int nn0 = (int)(m0 & 4095);
        size_t ob = ((size_t)(bi * 12 + hh) * 4096 + nn0) * 64 + dbase;
        for (int task = wid; task < 384; task += 8) {
            int mm = task / 3;
            int which = task - 3 * mm;
            float v = S[mm * S_ST + 3 * lane + which];
            size_t o = ob + (size_t)mm * 64 + lane;
            if (which == 0) g_q[o] = v;
            else {
                __half hv, lv; split2h(v, hv, lv);
                if (which == 1) { g_k_hi[o] = hv; g_k_lo[o] = lv; }
                else            { g_v_hi[o] = hv; g_v_lo[o] = lv; }
            }
        }
    } else if (mode == 1) {
        for (int task = wid; task < 384; task += 8) {
            int mm = task / 3;
            int g = task - 3 * mm;
            int cgl = n0 + g * 32 + lane;
            int hh = cgl >> 6, d = cgl & 63;
            int r = (int)m0 + mm;
            if (r < 1023) {
                __half hv, lv; split2h(S[mm * S_ST + g * 32 + lane], hv, lv);
                size_t o = ((size_t)hh * 1023 + r) * 64 + d;
                g_relk_hi[o] = hv; g_relk_lo[o] = lv;
            }
        }
    } else {
        for (int task = wid; task < 384; task += 8) {
            int mm = task / 3;
            int g = task - 3 * mm;
            int j = g * 32 + lane;
            Cout[(m0 + mm) * 768 + n0 + j] = S[mm * S_ST + j] + bias[n0 + j];
        }
    }
}

// merged QKV (1536 blocks) + relk (64 blocks)
__global__ __launch_bounds__(256, 2) void mma_gemm_merged() {
    int bid = blockIdx.x;
    if (bid < 1536)
        mma_gemm_body(bid % 24, bid / 24, g_x_hi, g_wqkv_hi, g_wqkv_lo,
                      nullptr, nullptr, 0);
    else {
        int rid = bid - 1536;
        mma_gemm_body(rid % 8, rid / 8, g_pos_hi, g_wrel_hi, g_wrel_lo,
                      nullptr, nullptr, 1);
    }
}

__global__ __launch_bounds__(256, 2) void mma_gemm_out(const float* __restrict__ bias,
                                                       float* __restrict__ Cout) {
    mma_gemm_body(blockIdx.x, blockIdx.y, g_att_hi, g_wout_hi, g_wout_lo,
                  bias, Cout, 2);
}

// ================= kernel 3: fp16 tensor-core fused window attention =================
// content QK: 2-product (Qh·Kh + Qh·Kl);  rel: 3-product (Qh·Rh + Qh·Rl + Ql·Rh);
// PV: 2-product (Ph·Vh + Ph·Vl). Blocked P layout keeps 32B geometry, lo half unused.
#define OFF_QCH 132096
#define OFF_KV  168960
#define OFF_RS  224256
#define ATT_SMEM 224512

__global__ __launch_bounds__(256) void attn_kernel(const float* __restrict__ rcb,
                                                   const float* __restrict__ rpb)
{
    extern __shared__ char smb[];
    float* S = (float*)smb;
    float* rs = (float*)(smb + OFF_RS);
    uint32_t sb = smem_u32(smb);
    int tid = threadIdx.x, wid = tid >> 5, lane = tid & 31;
    int wm = wid & 1, wn = wid >> 1;

    int tt = blockIdx.x & 7, win = blockIdx.x >> 3;
    int bN = win / 96, rem = win - bN * 96, h = rem >> 3, w = rem & 7;
    int t0 = tt << 6;
    size_t base = ((size_t)(bN * 12 + h)) * 4096 + (size_t)w * 512;
    const float* qb = g_q + (base + t0) * 64;
    const __half *kh = g_k_hi + base * 64, *klp = g_k_lo + base * 64;
    const __half *vh = g_v_hi + base * 64, *vlp = g_v_lo + base * 64;
    const __half *rh = g_relk_hi + (size_t)h * 1023 * 64;
    const __half *rlp = g_relk_lo + (size_t)h * 1023 * 64;
    int rbase = 448 - t0;

    auto fillChunk = [&](int ch) {
        int st = ch % 3;
        const __half *ph, *pl;
        int row0, rowmax;
        if (ch < 8)       { ph = kh; pl = klp; row0 = ch * 64; rowmax = 511; }
        else if (ch < 17) { ph = rh; pl = rlp; row0 = rbase + (ch - 8) * 64; rowmax = 1022; }
        else              { ph = vh; pl = vlp; row0 = (ch - 17) * 64; rowmax = 511; }
#pragma unroll
        for (int t = 0; t < 4; t++) {
            int i = tid + t * 256;
            int part = i >> 9, r = (i >> 3) & 63, cc = i & 7;
            int rr = row0 + r; if (rr > rowmax) rr = rowmax;
            const __half* src = (part ? pl : ph) + (size_t)rr * 64 + cc * 8;
            cp_async16(sb + OFF_KV + st * 18432 + part * 9216 + r * 144 + cc * 16, src);
        }
        cp_commit();
    };

    fillChunk(0);
    fillChunk(1);

    // q prep: +bias (fp32) -> qc hi (fp16) @ +0; qp hi @ +18432, qp lo @ +27648
    {
        int r = tid >> 2, c0 = (tid & 3) << 4;
#pragma unroll
        for (int i = 0; i < 4; i++) {
            int cc = c0 + i * 4;
            float4 qv = *(const float4*)(qb + r * 64 + cc);
            float4 bc = *(const float4*)(rcb + h * 64 + cc);
            float4 bp = *(const float4*)(rpb + h * 64 + cc);
            uint32_t off = r * 144 + cc * 2;
            *(uint32_t*)(smb + OFF_QCH + off)     = pack2h(qv.x + bc.x, qv.y + bc.y);
            *(uint32_t*)(smb + OFF_QCH + off + 4) = pack2h(qv.z + bc.z, qv.w + bc.w);
            uint32_t lo, hi;
            hi = pack_splith(qv.x + bp.x, qv.y + bp.y, lo);
            *(uint32_t*)(smb + OFF_QCH + 18432 + off) = hi;   *(uint32_t*)(smb + OFF_QCH + 27648 + off) = lo;
            hi = pack_splith(qv.z + bp.z, qv.w + bp.w, lo);
            *(uint32_t*)(smb + OFF_QCH + 18432 + off + 4) = hi; *(uint32_t*)(smb + OFF_QCH + 27648 + off + 4) = lo;
        }
    }

    float o[2][2][4];
#pragma unroll
    for (int a = 0; a < 2; a++)
#pragma unroll
        for (int bq = 0; bq < 2; bq++)
#pragma unroll
            for (int q = 0; q < 4; q++) o[a][bq][q] = 0.f;

    for (int c = 0; c < 25; c++) {
        if (c < 24) cp_wait1(); else cp_wait0();
        __syncthreads();

        if (c <= 22) fillChunk(c + 2);

        if (c == 17) {
            // softmax + in-place P fp16 hi conversion (blocked 32B layout, lo half unused)
            int r = tid >> 2, l4 = tid & 3;
            float* Sr = S + r * 516;
            float mx = -3.0e38f;
            for (int bq = l4; bq < 64; bq += 4) {
                float4 v0 = *(float4*)&Sr[bq * 8];
                float4 v1 = *(float4*)&Sr[bq * 8 + 4];
                mx = fmaxf(mx, fmaxf(fmaxf(v0.x, v0.y), fmaxf(v0.z, v0.w)));
                mx = fmaxf(mx, fmaxf(fmaxf(v1.x, v1.y), fmaxf(v1.z, v1.w)));
            }
            mx = fmaxf(mx, __shfl_xor_sync(0xffffffffu, mx, 1));
            mx = fmaxf(mx, __shfl_xor_sync(0xffffffffu, mx, 2));
            float sum = 0.f;
            for (int bq = l4; bq < 64; bq += 4) {
                float4 v0 = *(float4*)&Sr[bq * 8];
                float4 v1 = *(float4*)&Sr[bq * 8 + 4];
                float e0 = __expf(v0.x - mx), e1 = __expf(v0.y - mx);
                float e2 = __expf(v0.z - mx), e3 = __expf(v0.w - mx);
                float e4 = __expf(v1.x - mx), e5 = __expf(v1.y - mx);
                float e6 = __expf(v1.z - mx), e7 = __expf(v1.w - mx);
                sum += (e0 + e1 + e2 + e3) + (e4 + e5 + e6 + e7);
                uint4 hv;
                hv.x = pack2h(e0, e1); hv.y = pack2h(e2, e3);
                hv.z = pack2h(e4, e5); hv.w = pack2h(e6, e7);
                *(uint4*)((char*)Sr + bq * 32) = hv;
            }
            sum += __shfl_xor_sync(0xffffffffu, sum, 1);
            sum += __shfl_xor_sync(0xffffffffu, sum, 2);
            if (l4 == 0) rs[r] = sum;
            __syncthreads();
        }

        uint32_t kvh = sb + OFF_KV + (c % 3) * 18432;
        uint32_t kvl = kvh + 9216;

        if (c < 8) {
            // content QK: 2-product
            uint32_t qh = sb + OFF_QCH;
            float acc[2][2][4];
#pragma unroll
            for (int a = 0; a < 2; a++)
#pragma unroll
                for (int bq = 0; bq < 2; bq++)
#pragma unroll
                    for (int q = 0; q < 4; q++) acc[a][bq][q] = 0.f;
#pragma unroll
            for (int ks = 0; ks < 4; ks++) {
                uint32_t aoff = (32 * wm + (lane & 15)) * 144 + ks * 32 + ((lane >> 4) << 4);
                uint32_t Ah0[4], Ah1[4], Bh[4], Bl[4];
                ldsm4(Ah0, qh + aoff); ldsm4(Ah1, qh + aoff + 2304);
                uint32_t boff = (16 * wn + ((lane >> 4) << 3) + (lane & 7)) * 144
                              + ks * 32 + ((lane & 8) << 1);
                ldsm4(Bh, kvh + boff); ldsm4(Bl, kvl + boff);
                mma_f16f32(acc[0][0], Ah0, Bh[0], Bh[1]); mma_f16f32(acc[0][1], Ah0, Bh[2], Bh[3]);
                mma_f16f32(acc[1][0], Ah1, Bh[0], Bh[1]); mma_f16f32(acc[1][1], Ah1, Bh[2], Bh[3]);
                mma_f16f32(acc[0][0], Ah0, Bl[0], Bl[1]); mma_f16f32(acc[0][1], Ah0, Bl[2], Bl[3]);
                mma_f16f32(acc[1][0], Ah1, Bl[0], Bl[1]); mma_f16f32(acc[1][1], Ah1, Bl[2], Bl[3]);
            }
            int scol = c * 64 + 16 * wn;
#pragma unroll
            for (int mt = 0; mt < 2; mt++) {
                int t1 = 32 * wm + 16 * mt + (lane >> 2);
#pragma unroll
                for (int nt = 0; nt < 2; nt++) {
                    int col = scol + 8 * nt + ((lane & 3) << 1);
                    S[t1 * 516 + col]           = acc[mt][nt][0] * 0.125f;
                    S[t1 * 516 + col + 1]       = acc[mt][nt][1] * 0.125f;
                    S[(t1 + 8) * 516 + col]     = acc[mt][nt][2] * 0.125f;
                    S[(t1 + 8) * 516 + col + 1] = acc[mt][nt][3] * 0.125f;
                }
            }
        } else if (c < 17) {
            // rel: 3-product (fp16 limbs)
            uint32_t qh = sb + OFF_QCH + 18432, ql = qh + 9216;
            float acc[2][2][4];
#pragma unroll
            for (int a = 0; a < 2; a++)
#pragma unroll
                for (int bq = 0; bq < 2; bq++)
#pragma unroll
                    for (int q = 0; q < 4; q++) acc[a][bq][q] = 0.f;
#pragma unroll
            for (int ks = 0; ks < 4; ks++) {
                uint32_t aoff = (32 * wm + (lane & 15)) * 144 + ks * 32 + ((lane >> 4) << 4);
                uint32_t Ah0[4], Ah1[4], Al0[4], Al1[4], Bh[4], Bl[4];
                ldsm4(Ah0, qh + aoff); ldsm4(Ah1, qh + aoff + 2304);
                ldsm4(Al0, ql + aoff); ldsm4(Al1, ql + aoff + 2304);
                uint32_t boff = (16 * wn + ((lane >> 4) << 3) + (lane & 7)) * 144
                              + ks * 32 + ((lane & 8) << 1);
                ldsm4(Bh, kvh + boff); ldsm4(Bl, kvl + boff);
                mma_f16f32(acc[0][0], Ah0, Bh[0], Bh[1]); mma_f16f32(acc[0][1], Ah0, Bh[2], Bh[3]);
                mma_f16f32(acc[1][0], Ah1, Bh[0], Bh[1]); mma_f16f32(acc[1][1], Ah1, Bh[2], Bh[3]);
                mma_f16f32(acc[0][0], Ah0, Bl[0], Bl[1]); mma_f16f32(acc[0][1], Ah0, Bl[2], Bl[3]);
                mma_f16f32(acc[1][0], Ah1, Bl[0], Bl[1]); mma_f16f32(acc[1][1], Ah1, Bl[2], Bl[3]);
                mma_f16f32(acc[0][0], Al0, Bh[0], Bh[1]); mma_f16f32(acc[0][1], Al0, Bh[2], Bh[3]);
                mma_f16f32(acc[1][0], Al1, Bh[0], Bh[1]); mma_f16f32(acc[1][1], Al1, Bh[2], Bh[3]);
            }
            int colb = (c - 8) * 64 + 16 * wn;
#pragma unroll
            for (int mt = 0; mt < 2; mt++) {
                int t1 = 32 * wm + 16 * mt + (lane >> 2);
#pragma unroll
                for (int nt = 0; nt < 2; nt++) {
                    int rl0 = colb + 8 * nt + ((lane & 3) << 1);
                    int s1 = rl0 + t1 - 63;
                    if (s1 >= 0 && s1 < 512)         S[t1 * 516 + s1]           += acc[mt][nt][0];
                    if (s1 + 1 >= 0 && s1 + 1 < 512) S[t1 * 516 + s1 + 1]       += acc[mt][nt][1];
                    int s2 = s1 + 8;
                    if (s2 >= 0 && s2 < 512)         S[(t1 + 8) * 516 + s2]     += acc[mt][nt][2];
                    if (s2 + 1 >= 0 && s2 + 1 < 512) S[(t1 + 8) * 516 + s2 + 1] += acc[mt][nt][3];
                }
            }
        } else {
            // PV: 2-product (P hi only)
            int cv = c - 17;
#pragma unroll
            for (int ks = 0; ks < 4; ks++) {
                uint32_t aoff = (32 * wm + (lane & 15)) * 2064 + cv * 256 + ks * 64
                              + ((lane >> 4) << 5);
                uint32_t Ph0[4], Ph1[4], Vh[4], Vl[4];
                ldsm4(Ph0, sb + aoff); ldsm4(Ph1, sb + aoff + 33024);
                int g = lane >> 3;
                uint32_t boff = (ks * 16 + ((g & 1) << 3) + (lane & 7)) * 144
                              + 32 * wn + ((g >> 1) << 4);
                ldsm4t(Vh, kvh + boff); ldsm4t(Vl, kvl + boff);
                mma_f16f32(o[0][0], Ph0, Vh[0], Vh[1]); mma_f16f32(o[0][1], Ph0, Vh[2], Vh[3]);
                mma_f16f32(o[1][0], Ph1, Vh[0], Vh[1]); mma_f16f32(o[1][1], Ph1, Vh[2], Vh[3]);
                mma_f16f32(o[0][0], Ph0, Vl[0], Vl[1]); mma_f16f32(o[0][1], Ph0, Vl[2], Vl[3]);
                mma_f16f32(o[1][0], Ph1, Vl[0], Vl[1]); mma_f16f32(o[1][1], Ph1, Vl[2], Vl[3]);
            }
        }
    }

    // normalize + write fp16 hi (A operand of 2-product out-proj GEMM)
    int colc = 16 * wn;
#pragma unroll
    for (int mt = 0; mt < 2; mt++) {
        int t1 = 32 * wm + 16 * mt + (lane >> 2);
        float i1 = 1.f / rs[t1], i2 = 1.f / rs[t1 + 8];
        size_t row1 = (size_t)bN * 4096 + (size_t)w * 512 + t0 + t1;
#pragma unroll
        for (int nt = 0; nt < 2; nt++) {
            int col = colc + 8 * nt + ((lane & 3) << 1);
            size_t off1 = row1 * 768 + h * 64 + col;
            size_t off2 = (row1 + 8) * 768 + h * 64 + col;
            *(uint32_t*)(g_att_hi + off1) = pack2h(o[mt][nt][0] * i1, o[mt][nt][1] * i1);
            *(uint32_t*)(g_att_hi + off2) = pack2h(o[mt][nt][2] * i2, o[mt][nt][3] * i2);
        }
    }
}

// ================= launch =================
extern "C" void kernel_launch(void* const* d_in, const int* in_sizes, int n_in,
                              void* d_out, int out_size)
{
    const float* x     = (const float*)d_in[0];
    const float* w_qkv = (const float*)d_in[1];
    const float* w_out = (const float*)d_in[2];
    const float* b_out = (const float*)d_in[3];
    const float* w_rel = (const float*)d_in[4];
    const float* rcb   = (const float*)d_in[5];
    const float* rpb   = (const float*)d_in[6];
    float* out = (float*)d_out;

    cudaFuncSetAttribute(attn_kernel, cudaFuncAttributeMaxDynamicSharedMemorySize, ATT_SMEM);
    cudaFuncSetAttribute(mma_gemm_merged, cudaFuncAttributeMaxDynamicSharedMemorySize, GEMM_SMEM);
    cudaFuncSetAttribute(mma_gemm_out, cudaFuncAttributeMaxDynamicSharedMemorySize, GEMM_SMEM);

    prep_kernel<<<5440, 256>>>(x, w_qkv, w_out, w_rel);
    mma_gemm_merged<<<1600, 256, GEMM_SMEM>>>();
    attn_kernel<<<1536, 256, ATT_SMEM>>>(rcb, rpb);
    mma_gemm_out<<<dim3(8, 64), 256, GEMM_SMEM>>>(b_out, out);
}

// round 17
// speedup vs baseline: 1.3630x; 1.0547x over previous
#include <cuda_runtime.h>
#include <cuda_fp16.h>
#include <math.h>
#include <stdint.h>

// ================= scratch (device globals) =================
__device__ float g_q[6291456];                         // [B*H][4096][64] fp32
__device__ __half g_k_hi[6291456];                     // attn K (fp16, single limb)
__device__ __half g_v_hi[6291456];                     // attn V (fp16, single limb)
__device__ __half g_relk_hi[12 * 1023 * 64], g_relk_lo[12 * 1023 * 64];

__device__ __half g_x_hi[8192 * 768];                           // GEMM A operands (fp16 hi only)
__device__ __half g_wqkv_hi[2304 * 768], g_wqkv_lo[2304 * 768]; // [N][K] fp16 hi/lo
__device__ __half g_wout_hi[768 * 768],  g_wout_lo[768 * 768];
__device__ __half g_wrel_hi[768 * 768],  g_wrel_lo[768 * 768];
__device__ __half g_pos_hi[1024 * 768];                         // row 1023 stays zero
__device__ __half g_att_hi[8192 * 768];

// ================= helpers =================
__device__ __forceinline__ uint32_t smem_u32(const void* p) {
    uint32_t a;
    asm("{ .reg .u64 t; cvta.to.shared.u64 t, %1; cvt.u32.u64 %0, t; }" : "=r"(a) : "l"(p));
    return a;
}
__device__ __forceinline__ void cp_async16(uint32_t dst, const void* src) {
    asm volatile("cp.async.ca.shared.global [%0], [%1], 16;" :: "r"(dst), "l"(src));
}
__device__ __forceinline__ void cp_commit() { asm volatile("cp.async.commit_group;"); }
__device__ __forceinline__ void cp_wait1() { asm volatile("cp.async.wait_group 1;"); }
__device__ __forceinline__ void cp_wait0() { asm volatile("cp.async.wait_group 0;"); }

__device__ __forceinline__ void ldsm4(uint32_t* r, uint32_t addr) {
    asm volatile("ldmatrix.sync.aligned.m8n8.x4.shared.b16 {%0,%1,%2,%3}, [%4];"
                 : "=r"(r[0]), "=r"(r[1]), "=r"(r[2]), "=r"(r[3]) : "r"(addr));
}
__device__ __forceinline__ void ldsm4t(uint32_t* r, uint32_t addr) {
    asm volatile("ldmatrix.sync.aligned.m8n8.x4.trans.shared.b16 {%0,%1,%2,%3}, [%4];"
                 : "=r"(r[0]), "=r"(r[1]), "=r"(r[2]), "=r"(r[3]) : "r"(addr));
}
// fp16 MMA with fp32 accumulate
__device__ __forceinline__ void mma_f16f32(float* d, const uint32_t* a, uint32_t b0, uint32_t b1) {
    asm volatile("mma.sync.aligned.m16n8k16.row.col.f32.f16.f16.f32 "
                 "{%0,%1,%2,%3}, {%4,%5,%6,%7}, {%8,%9}, {%0,%1,%2,%3};"
                 : "+f"(d[0]), "+f"(d[1]), "+f"(d[2]), "+f"(d[3])
                 : "r"(a[0]), "r"(a[1]), "r"(a[2]), "r"(a[3]), "r"(b0), "r"(b1));
}
__device__ __forceinline__ void split2h(float v, __half& h, __half& l) {
    h = __float2half_rn(v);
    l = __float2half_rn(v - __half2float(h));
}
__device__ __forceinline__ uint32_t pack_splith(float a, float b, uint32_t& lo) {
    __half2 h = __floats2half2_rn(a, b);
    float ra = __half2float(__low2half(h));
    float rb = __half2float(__high2half(h));
    __half2 l = __floats2half2_rn(a - ra, b - rb);
    lo = *(uint32_t*)&l;
    return *(uint32_t*)&h;
}
__device__ __forceinline__ uint32_t pack2h(float a, float b) {
    __half2 h = __floats2half2_rn(a, b);
    return *(uint32_t*)&h;
}

// ================= kernel 1: merged prologue =================
__device__ __forceinline__ void splitT_body(const float* __restrict__ src,
                                            __half* __restrict__ hi,
                                            __half* __restrict__ lo,
                                            int K, int N, int bx, int by, int tid,
                                            float (*t)[33]) {
    int n0 = bx * 32, k0 = by * 32;
    int x = tid & 31, y0 = tid >> 5;
#pragma unroll
    for (int i = 0; i < 4; i++) {
        int y = y0 + i * 8;
        t[y][x] = src[(size_t)(k0 + y) * N + n0 + x];
    }
    __syncthreads();
#pragma unroll
    for (int i = 0; i < 4; i++) {
        int y = y0 + i * 8;
        float v = t[x][y];
        __half a, b;
        split2h(v, a, b);
        size_t o = (size_t)(n0 + y) * K + k0 + x;
        hi[o] = a; lo[o] = b;
    }
}

__global__ __launch_bounds__(256) void prep_kernel(
    const float* __restrict__ x, const float* __restrict__ w_qkv,
    const float* __restrict__ w_out, const float* __restrict__ w_rel)
{
    __shared__ float t[32][33];
    __shared__ double red[2][128];
    int bid = blockIdx.x, tid = threadIdx.x;

    if (bid < 2048) {
#pragma unroll
        for (int it = 0; it < 12; it++) {
            int i = (bid * 12 + it) * 256 + tid;
            g_x_hi[i] = __float2half_rn(x[i]);
        }
    } else if (bid < 3776) {
        int rid = bid - 2048;
        splitT_body(w_qkv, g_wqkv_hi, g_wqkv_lo, 768, 2304, rid % 72, rid / 72, tid, t);
    } else if (bid < 4352) {
        int rid = bid - 3776;
        splitT_body(w_out, g_wout_hi, g_wout_lo, 768, 768, rid % 24, rid / 24, tid, t);
    } else if (bid < 4928) {
        int rid = bid - 4352;
        splitT_body(w_rel, g_wrel_hi, g_wrel_lo, 768, 768, rid % 24, rid / 24, tid, t);
    } else {
        int half = tid >> 7, j = tid & 127;
        int r = (bid - 4928) * 2 + half;
        int rr = (r < 1023) ? r : 1022;
        float dist = (float)(rr - 511);
        double p = fabs((double)dist);

        double hl = exp2(3.0 + (double)j * (6.0 / 127.0));
        float ef = (float)exp(-0.6931471805599453 / hl * p);

        float cw = exp2f((float)(j + 1)) - 1.0f;
        float cm = (cw > (float)p) ? 1.0f : 0.0f;

        double mean = 4.0 * (double)(j + 1);
        double conc = (mean * 0.5) * (mean * 0.5);
        double rate = mean * 0.25;
        double lp = -rate * p - (lgamma(conc) - conc * log(rate));
        if (p > 0.0) lp += (conc - 1.0) * log(p);
        double prob = ((p > 0.0) ? exp(lp) : 0.0) + 1e-8;  // xlogy(c-1,0) -> -inf -> 0

        red[half][j] = prob;
        __syncthreads();
        for (int o = 64; o > 0; o >>= 1) {
            if (j < o) red[half][j] = fmax(red[half][j], red[half][j + o]);
            __syncthreads();
        }
        float gf = (float)(prob / red[half][0]);

        float sg = (dist > 0.f) ? 1.f : ((dist < 0.f) ? -1.f : 0.f);
        float vals[6] = {ef, cm, gf, sg * ef, sg * cm, sg * gf};
        if (r < 1023) {
            size_t base = (size_t)r * 768;
#pragma unroll
            for (int s = 0; s < 6; s++)
                g_pos_hi[base + s * 128 + j] = __float2half_rn(vals[s]);
        }
    }
}

// ================= fp16 2-product GEMM body (128x96 tile, 2 CTAs/SM) =================
#define APB 10240
#define BPB 7680
#define STG 25600
#define GEMM_SMEM (2 * STG)
#define S_ST 100

__device__ __forceinline__ void mma_gemm_body(
    int bx, int by,
    const __half* __restrict__ Ah,
    const __half* __restrict__ Bh, const __half* __restrict__ Bl,
    const float* __restrict__ bias, float* __restrict__ Cout, int mode)
{
    extern __shared__ char dsm[];
    uint32_t sbase = smem_u32(dsm);
    int tid = threadIdx.x, wid = tid >> 5, lane = tid & 31;
    int wm = wid & 3, wn = wid >> 2;

    size_t m0 = (size_t)by * 128;
    int n0 = bx * 96;

    float acc[2][6][4];
#pragma unroll
    for (int i = 0; i < 2; i++)
#pragma unroll
        for (int j = 0; j < 6; j++)
#pragma unroll
            for (int q = 0; q < 4; q++) acc[i][j][q] = 0.f;

    int a_lr = lane & 15;
    int a_lc = (lane >> 4) << 3;
    int b_ln = ((lane >> 4) << 3) + (lane & 7);
    int b_lk = lane & 8;

    auto fill = [&](int s, int c) {
        uint32_t st = sbase + s * STG;
        int k0 = c * 32;
#pragma unroll
        for (int ii = 0; ii < 5; ii++) {
            int i = tid + ii * 256;
            if (i < 512) {
                int rr = i >> 2, cc = i & 3;
                cp_async16(st + rr * 80 + cc * 16, Ah + (m0 + rr) * 768 + k0 + cc * 8);
            } else {
                int j = i - 512;
                int part = j >= 384; int jj = j - (part ? 384 : 0);
                int rr = jj >> 2, cc = jj & 3;
                const __half* src = (part ? Bl : Bh) + (size_t)(n0 + rr) * 768 + k0 + cc * 8;
                cp_async16(st + APB + part * BPB + rr * 80 + cc * 16, src);
            }
        }
        cp_commit();
    };

    fill(0, 0);
    for (int c = 0; c < 24; c++) {
        if (c < 23) { fill((c + 1) & 1, c + 1); cp_wait1(); } else { cp_wait0(); }
        __syncthreads();

        uint32_t st = sbase + (c & 1) * STG;
#pragma unroll
        for (int step = 0; step < 2; step++) {
            uint32_t ab = st + (wm * 32 + a_lr) * 80 + (step * 16 + a_lc) * 2;
            uint32_t bb = st + APB + (wn * 48 + b_ln) * 80 + (step * 16 + b_lk) * 2;
            uint32_t Af[2][4], Bf[3][4], Blf[3][4];
            ldsm4(Af[0], ab); ldsm4(Af[1], ab + 1280);
#pragma unroll
            for (int ng = 0; ng < 3; ng++) {
                ldsm4(Bf[ng],  bb + ng * 1280);
                ldsm4(Blf[ng], bb + BPB + ng * 1280);
            }
#pragma unroll
            for (int mi = 0; mi < 2; mi++)
#pragma unroll
                for (int ng = 0; ng < 3; ng++) {
                    mma_f16f32(acc[mi][ng * 2 + 0], Af[mi], Bf[ng][0], Bf[ng][1]);
                    mma_f16f32(acc[mi][ng * 2 + 1], Af[mi], Bf[ng][2], Bf[ng][3]);
                }
#pragma unroll
            for (int mi = 0; mi < 2; mi++)
#pragma unroll
                for (int ng = 0; ng < 3; ng++) {
                    mma_f16f32(acc[mi][ng * 2 + 0], Af[mi], Blf[ng][0], Blf[ng][1]);
                    mma_f16f32(acc[mi][ng * 2 + 1], Af[mi], Blf[ng][2], Blf[ng][3]);
                }
        }
        __syncthreads();
    }

    float* S = (float*)dsm;
#pragma unroll
    for (int mi = 0; mi < 2; mi++)
#pragma unroll
        for (int nj = 0; nj < 6; nj++) {
            int row = wm * 32 + mi * 16 + (lane >> 2);
            int col = wn * 48 + nj * 8 + (lane & 3) * 2;
            S[row * S_ST + col]             = acc[mi][nj][0];
            S[row * S_ST + col + 1]         = acc[mi][nj][1];
            S[(row + 8) * S_ST + col]       = acc[mi][nj][2];
            S[(row + 8) * S_ST + col + 1]   = acc[mi][nj][3];
        }
    __syncthreads();

    if (mode == 0) {
        int hh = bx >> 1;
        int dbase = (bx & 1) * 32;
        int bi = (int)(m0 >> 12);
        int nn0 = (int)(m0 & 4095);
        size_t ob = ((size_t)(bi * 12 + hh) * 4096 + nn0) * 64 + dbase;
        for (int task = wid; task < 384; task += 8) {
            int mm = task / 3;
            int which = task - 3 * mm;
            float v = S[mm * S_ST + 3 * lane + which];
            size_t o = ob + (size_t)mm * 64 + lane;
            if (which == 0) g_q[o] = v;
            else if (which == 1) g_k_hi[o] = __float2half_rn(v);
            else                 g_v_hi[o] = __float2half_rn(v);
        }
    } else if (mode == 1) {
        for (int task = wid; task < 384; task += 8) {
            int mm = task / 3;
            int g = task - 3 * mm;
            int cgl = n0 + g * 32 + lane;
            int hh = cgl >> 6, d = cgl & 63;
            int r = (int)m0 + mm;
            if (r < 1023) {
                __half hv, lv; split2h(S[mm * S_ST + g * 32 + lane], hv, lv);
                size_t o = ((size_t)hh * 1023 + r) * 64 + d;
                g_relk_hi[o] = hv; g_relk_lo[o] = lv;
            }
        }
    } else {
        for (int task = wid; task < 384; task += 8) {
            int mm = task / 3;
            int g = task - 3 * mm;
            int j = g * 32 + lane;
            Cout[(m0 + mm) * 768 + n0 + j] = S[mm * S_ST + j] + bias[n0 + j];
        }
    }
}

// merged QKV (1536 blocks) + relk (64 blocks)
__global__ __launch_bounds__(256, 2) void mma_gemm_merged() {
    int bid = blockIdx.x;
    if (bid < 1536)
        mma_gemm_body(bid % 24, bid / 24, g_x_hi, g_wqkv_hi, g_wqkv_lo,
                      nullptr, nullptr, 0);
    else {
        int rid = bid - 1536;
        mma_gemm_body(rid % 8, rid / 8, g_pos_hi, g_wrel_hi, g_wrel_lo,
                      nullptr, nullptr, 1);
    }
}

__global__ __launch_bounds__(256, 2) void mma_gemm_out(const float* __restrict__ bias,
                                                       float* __restrict__ Cout) {
    mma_gemm_body(blockIdx.x, blockIdx.y, g_att_hi, g_wout_hi, g_wout_lo,
                  bias, Cout, 2);
}

// ================= kernel 3: fp16 tensor-core fused window attention =================
// QK: 1-product (Qh·Kh); rel: 3-product (Qh·Rh + Qh·Rl + Ql·Rh); PV: 1-product (Ph·Vh).
// K/V chunks load hi only (8KB); rel chunks load hi+lo (16KB).
#define OFF_QCH 132096
#define OFF_KV  168960
#define OFF_RS  224256
#define ATT_SMEM 224512

__global__ __launch_bounds__(256) void attn_kernel(const float* __restrict__ rcb,
                                                   const float* __restrict__ rpb)
{
    extern __shared__ char smb[];
    float* S = (float*)smb;
    float* rs = (float*)(smb + OFF_RS);
    uint32_t sb = smem_u32(smb);
    int tid = threadIdx.x, wid = tid >> 5, lane = tid & 31;
    int wm = wid & 1, wn = wid >> 1;

    int tt = blockIdx.x & 7, win = blockIdx.x >> 3;
    int bN = win / 96, rem = win - bN * 96, h = rem >> 3, w = rem & 7;
    int t0 = tt << 6;
    size_t base = ((size_t)(bN * 12 + h)) * 4096 + (size_t)w * 512;
    const float* qb = g_q + (base + t0) * 64;
    const __half *kh = g_k_hi + base * 64;
    const __half *vh = g_v_hi + base * 64;
    const __half *rh = g_relk_hi + (size_t)h * 1023 * 64;
    const __half *rlp = g_relk_lo + (size_t)h * 1023 * 64;
    int rbase = 448 - t0;

    auto fillChunk = [&](int ch) {
        int st = ch % 3;
        if (ch >= 8 && ch < 17) {
            // rel: hi + lo (16KB)
            int row0 = rbase + (ch - 8) * 64;
#pragma unroll
            for (int t = 0; t < 4; t++) {
                int i = tid + t * 256;
                int part = i >> 9, r = (i >> 3) & 63, cc = i & 7;
                int rr = row0 + r; if (rr > 1022) rr = 1022;
                const __half* src = (part ? rlp : rh) + (size_t)rr * 64 + cc * 8;
                cp_async16(sb + OFF_KV + st * 18432 + part * 9216 + r * 144 + cc * 16, src);
            }
        } else {
            // K or V: hi only (8KB)
            const __half* ph = (ch < 8) ? kh : vh;
            int row0 = (ch < 8) ? ch * 64 : (ch - 17) * 64;
#pragma unroll
            for (int t = 0; t < 2; t++) {
                int i = tid + t * 256;
                int r = i >> 3, cc = i & 7;
                cp_async16(sb + OFF_KV + st * 18432 + r * 144 + cc * 16,
                           ph + (size_t)(row0 + r) * 64 + cc * 8);
            }
        }
        cp_commit();
    };

    fillChunk(0);
    fillChunk(1);

    // q prep: +bias (fp32) -> qc hi (fp16) @ +0; qp hi @ +18432, qp lo @ +27648
    {
        int r = tid >> 2, c0 = (tid & 3) << 4;
#pragma unroll
        for (int i = 0; i < 4; i++) {
            int cc = c0 + i * 4;
            float4 qv = *(const float4*)(qb + r * 64 + cc);
            float4 bc = *(const float4*)(rcb + h * 64 + cc);
            float4 bp = *(const float4*)(rpb + h * 64 + cc);
            uint32_t off = r * 144 + cc * 2;
            *(uint32_t*)(smb + OFF_QCH + off)     = pack2h(qv.x + bc.x, qv.y + bc.y);
            *(uint32_t*)(smb + OFF_QCH + off + 4) = pack2h(qv.z + bc.z, qv.w + bc.w);
            uint32_t lo, hi;
            hi = pack_splith(qv.x + bp.x, qv.y + bp.y, lo);
            *(uint32_t*)(smb + OFF_QCH + 18432 + off) = hi;   *(uint32_t*)(smb + OFF_QCH + 27648 + off) = lo;
            hi = pack_splith(qv.z + bp.z, qv.w + bp.w, lo);
            *(uint32_t*)(smb + OFF_QCH + 18432 + off + 4) = hi; *(uint32_t*)(smb + OFF_QCH + 27648 + off + 4) = lo;
        }
    }

    float o[2][2][4];
#pragma unroll
    for (int a = 0; a < 2; a++)
#pragma unroll
        for (int bq = 0; bq < 2; bq++)
#pragma unroll
            for (int q = 0; q < 4; q++) o[a][bq][q] = 0.f;

    for (int c = 0; c < 25; c++) {
        if (c < 24) cp_wait1(); else cp_wait0();
        __syncthreads();

        if (c <= 22) fillChunk(c + 2);

        if (c == 17) {
            // softmax + in-place P fp16 hi conversion (blocked 32B layout, lo half unused)
            int r = tid >> 2, l4 = tid & 3;
            float* Sr = S + r * 516;
            float mx = -3.0e38f;
            for (int bq = l4; bq < 64; bq += 4) {
                float4 v0 = *(float4*)&Sr[bq * 8];
                float4 v1 = *(float4*)&Sr[bq * 8 + 4];
                mx = fmaxf(mx, fmaxf(fmaxf(v0.x, v0.y), fmaxf(v0.z, v0.w)));
                mx = fmaxf(mx, fmaxf(fmaxf(v1.x, v1.y), fmaxf(v1.z, v1.w)));
            }
            mx = fmaxf(mx, __shfl_xor_sync(0xffffffffu, mx, 1));
            mx = fmaxf(mx, __shfl_xor_sync(0xffffffffu, mx, 2));
            float sum = 0.f;
            for (int bq = l4; bq < 64; bq += 4) {
                float4 v0 = *(float4*)&Sr[bq * 8];
                float4 v1 = *(float4*)&Sr[bq * 8 + 4];
                float e0 = __expf(v0.x - mx), e1 = __expf(v0.y - mx);
                float e2 = __expf(v0.z - mx), e3 = __expf(v0.w - mx);
                float e4 = __expf(v1.x - mx), e5 = __expf(v1.y - mx);
                float e6 = __expf(v1.z - mx), e7 = __expf(v1.w - mx);
                sum += (e0 + e1 + e2 + e3) + (e4 + e5 + e6 + e7);
                uint4 hv;
                hv.x = pack2h(e0, e1); hv.y = pack2h(e2, e3);
                hv.z = pack2h(e4, e5); hv.w = pack2h(e6, e7);
                *(uint4*)((char*)Sr + bq * 32) = hv;
            }
            sum += __shfl_xor_sync(0xffffffffu, sum, 1);
            sum += __shfl_xor_sync(0xffffffffu, sum, 2);
            if (l4 == 0) rs[r] = sum;
            __syncthreads();
        }

        uint32_t kvh = sb + OFF_KV + (c % 3) * 18432;
        uint32_t kvl = kvh + 9216;

        if (c < 8) {
            // content QK: 1-product
            uint32_t qh = sb + OFF_QCH;
            float acc[2][2][4];
#pragma unroll
            for (int a = 0; a < 2; a++)
#pragma unroll
                for (int bq = 0; bq < 2; bq++)
#pragma unroll
                    for (int q = 0; q < 4; q++) acc[a][bq][q] = 0.f;
#pragma unroll
            for (int ks = 0; ks < 4; ks++) {
                uint32_t aoff = (32 * wm + (lane & 15)) * 144 + ks * 32 + ((lane >> 4) << 4);
                uint32_t Ah0[4], Ah1[4], Bh[4];
                ldsm4(Ah0, qh + aoff); ldsm4(Ah1, qh + aoff + 2304);
                uint32_t boff = (16 * wn + ((lane >> 4) << 3) + (lane & 7)) * 144
                              + ks * 32 + ((lane & 8) << 1);
                ldsm4(Bh, kvh + boff);
                mma_f16f32(acc[0][0], Ah0, Bh[0], Bh[1]); mma_f16f32(acc[0][1], Ah0, Bh[2], Bh[3]);
                mma_f16f32(acc[1][0], Ah1, Bh[0], Bh[1]); mma_f16f32(acc[1][1], Ah1, Bh[2], Bh[3]);
            }
            int scol = c * 64 + 16 * wn;
#pragma unroll
            for (int mt = 0; mt < 2; mt++) {
                int t1 = 32 * wm + 16 * mt + (lane >> 2);
#pragma unroll
                for (int nt = 0; nt < 2; nt++) {
                    int col = scol + 8 * nt + ((lane & 3) << 1);
                    S[t1 * 516 + col]           = acc[mt][nt][0] * 0.125f;
                    S[t1 * 516 + col + 1]       = acc[mt][nt][1] * 0.125f;
                    S[(t1 + 8) * 516 + col]     = acc[mt][nt][2] * 0.125f;
                    S[(t1 + 8) * 516 + col + 1] = acc[mt][nt][3] * 0.125f;
                }
            }
        } else if (c < 17) {
            // rel: 3-product (fp16 limbs)
            uint32_t qh = sb + OFF_QCH + 18432, ql = qh + 9216;
            float acc[2][2][4];
#pragma unroll
            for (int a = 0; a < 2; a++)
#pragma unroll
                for (int bq = 0; bq < 2; bq++)
#pragma unroll
                    for (int q = 0; q < 4; q++) acc[a][bq][q] = 0.f;
#pragma unroll
            for (int ks = 0; ks < 4; ks++) {
                uint32_t aoff = (32 * wm + (lane & 15)) * 144 + ks * 32 + ((lane >> 4) << 4);
                uint32_t Ah0[4], Ah1[4], Al0[4], Al1[4], Bh[4], Bl[4];
                ldsm4(Ah0, qh + aoff); ldsm4(Ah1, qh + aoff + 2304);
                ldsm4(Al0, ql + aoff); ldsm4(Al1, ql + aoff + 2304);
                uint32_t boff = (16 * wn + ((lane >> 4) << 3) + (lane & 7)) * 144
                              + ks * 32 + ((lane & 8) << 1);
                ldsm4(Bh, kvh + boff); ldsm4(Bl, kvl + boff);
                mma_f16f32(acc[0][0], Ah0, Bh[0], Bh[1]); mma_f16f32(acc[0][1], Ah0, Bh[2], Bh[3]);
                mma_f16f32(acc[1][0], Ah1, Bh[0], Bh[1]); mma_f16f32(acc[1][1], Ah1, Bh[2], Bh[3]);
                mma_f16f32(acc[0][0], Ah0, Bl[0], Bl[1]); mma_f16f32(acc[0][1], Ah0, Bl[2], Bl[3]);
                mma_f16f32(acc[1][0], Ah1, Bl[0], Bl[1]); mma_f16f32(acc[1][1], Ah1, Bl[2], Bl[3]);
                mma_f16f32(acc[0][0], Al0, Bh[0], Bh[1]); mma_f16f32(acc[0][1], Al0, Bh[2], Bh[3]);
                mma_f16f32(acc[1][0], Al1, Bh[0], Bh[1]); mma_f16f32(acc[1][1], Al1, Bh[2], Bh[3]);
            }
            int colb = (c - 8) * 64 + 16 * wn;
#pragma unroll
            for (int mt = 0; mt < 2; mt++) {
                int t1 = 32 * wm + 16 * mt + (lane >> 2);
#pragma unroll
                for (int nt = 0; nt < 2; nt++) {
                    int rl0 = colb + 8 * nt + ((lane & 3) << 1);
                    int s1 = rl0 + t1 - 63;
                    if (s1 >= 0 && s1 < 512)         S[t1 * 516 + s1]           += acc[mt][nt][0];
                    if (s1 + 1 >= 0 && s1 + 1 < 512) S[t1 * 516 + s1 + 1]       += acc[mt][nt][1];
                    int s2 = s1 + 8;
                    if (s2 >= 0 && s2 < 512)         S[(t1 + 8) * 516 + s2]     += acc[mt][nt][2];
                    if (s2 + 1 >= 0 && s2 + 1 < 512) S[(t1 + 8) * 516 + s2 + 1] += acc[mt][nt][3];
                }
            }
        } else {
            // PV: 1-product (P hi, V hi)
            int cv = c - 17;
#pragma unroll
            for (int ks = 0; ks < 4; ks++) {
                uint32_t aoff = (32 * wm + (lane & 15)) * 2064 + cv * 256 + ks * 64
                              + ((lane >> 4) << 5);
                uint32_t Ph0[4], Ph1[4], Vh[4];
                ldsm4(Ph0, sb + aoff); ldsm4(Ph1, sb + aoff + 33024);
                int g = lane >> 3;
                uint32_t boff = (ks * 16 + ((g & 1) << 3) + (lane & 7)) * 144
                              + 32 * wn + ((g >> 1) << 4);
                ldsm4t(Vh, kvh + boff);
                mma_f16f32(o[0][0], Ph0, Vh[0], Vh[1]); mma_f16f32(o[0][1], Ph0, Vh[2], Vh[3]);
                mma_f16f32(o[1][0], Ph1, Vh[0], Vh[1]); mma_f16f32(o[1][1], Ph1, Vh[2], Vh[3]);
            }
        }
    }

    // normalize + write fp16 hi (A operand of 2-product out-proj GEMM)
    int colc = 16 * wn;
#pragma unroll
    for (int mt = 0; mt < 2; mt++) {
        int t1 = 32 * wm + 16 * mt + (lane >> 2);
        float i1 = 1.f / rs[t1], i2 = 1.f / rs[t1 + 8];
        size_t row1 = (size_t)bN * 4096 + (size_t)w * 512 + t0 + t1;
#pragma unroll
        for (int nt = 0; nt < 2; nt++) {
            int col = colc + 8 * nt + ((lane & 3) << 1);
            size_t off1 = row1 * 768 + h * 64 + col;
            size_t off2 = (row1 + 8) * 768 + h * 64 + col;
            *(uint32_t*)(g_att_hi + off1) = pack2h(o[mt][nt][0] * i1, o[mt][nt][1] * i1);
            *(uint32_t*)(g_att_hi + off2) = pack2h(o[mt][nt][2] * i2, o[mt][nt][3] * i2);
        }
    }
}

// ================= launch =================
extern "C" void kernel_launch(void* const* d_in, const int* in_sizes, int n_in,
                              void* d_out, int out_size)
{
    const float* x     = (const float*)d_in[0];
    const float* w_qkv = (const float*)d_in[1];
    const float* w_out = (const float*)d_in[2];
    const float* b_out = (const float*)d_in[3];
    const float* w_rel = (const float*)d_in[4];
    const float* rcb   = (const float*)d_in[5];
    const float* rpb   = (const float*)d_in[6];
    float* out = (float*)d_out;

    cudaFuncSetAttribute(attn_kernel, cudaFuncAttributeMaxDynamicSharedMemorySize, ATT_SMEM);
    cudaFuncSetAttribute(mma_gemm_merged, cudaFuncAttributeMaxDynamicSharedMemorySize, GEMM_SMEM);
    cudaFuncSetAttribute(mma_gemm_out, cudaFuncAttributeMaxDynamicSharedMemorySize, GEMM_SMEM);

    prep_kernel<<<5440, 256>>>(x, w_qkv, w_out, w_rel);
    mma_gemm_merged<<<1600, 256, GEMM_SMEM>>>();
    attn_kernel<<<1536, 256, ATT_SMEM>>>(rcb, rpb);
    mma_gemm_out<<<dim3(8, 64), 256, GEMM_SMEM>>>(b_out, out);
}